// round 12
// baseline (speedup 1.0000x reference)
#include <cuda_runtime.h>
#include <cuda_bf16.h>
#include <cstdint>

#define BB 200000      // batch size
#define NN 400000      // nodes = 2*BB
#define DD 128         // embedding dim
#define PITCH 136      // padded bf16 pitch for smem tiles
#define TM 64          // GEMM tile rows per CTA
#define NTHR 128       // threads per GEMM CTA (4 warps)
#define NCOMP 200000   // useful rows, compact: [0,100k) u [200k,300k)
#define NE (2 * BB)    // directed edges

// ---------------- scratch (device globals; no allocs allowed) ----------------
__device__ float g_deg[NN];                       // degree -> dinv (in place)
__device__ float g_H [(size_t)NN * DD];           // buffer C (H1)
__device__ float g_P0[(size_t)NN * DD];           // buffer A
__device__ float g_P1[(size_t)NN * DD];           // buffer B
__device__ __align__(16) char g_Wt_hi[3][128 * PITCH * 2];
__device__ __align__(16) char g_Wt_lo[3][128 * PITCH * 2];
__device__ int  g_off[NCOMP + 1];                 // CSR offsets (compact)
__device__ int  g_cur[NCOMP];                     // fill cursors
__device__ int  g_bsum[800];                      // scan block sums
__device__ int2 g_edge[NE];                       // (nbr position, norm bits)

// ---------------- helpers ----------------
__device__ __forceinline__ uint32_t smem_u32(const void* p) {
    uint32_t a;
    asm("{ .reg .u64 t; cvta.to.shared.u64 t, %1; cvt.u32.u64 %0, t; }" : "=r"(a) : "l"(p));
    return a;
}
__device__ __forceinline__ void cp_async16(uint32_t dst, const void* src) {
    asm volatile("cp.async.cg.shared.global [%0], [%1], 16;" :: "r"(dst), "l"(src) : "memory");
}
__device__ __forceinline__ void ldm_x4(uint32_t a, uint32_t& r0, uint32_t& r1,
                                       uint32_t& r2, uint32_t& r3) {
    asm volatile("ldmatrix.sync.aligned.m8n8.x4.shared.b16 {%0,%1,%2,%3}, [%4];"
                 : "=r"(r0), "=r"(r1), "=r"(r2), "=r"(r3) : "r"(a));
}
__device__ __forceinline__ void mma_bf16(float* c, const uint32_t* a, uint32_t b0, uint32_t b1) {
    asm volatile("mma.sync.aligned.m16n8k16.row.col.f32.bf16.bf16.f32 "
                 "{%0,%1,%2,%3}, {%4,%5,%6,%7}, {%8,%9}, {%0,%1,%2,%3};"
                 : "+f"(c[0]), "+f"(c[1]), "+f"(c[2]), "+f"(c[3])
                 : "r"(a[0]), "r"(a[1]), "r"(a[2]), "r"(a[3]), "r"(b0), "r"(b1));
}
__device__ __forceinline__ bool h_useful(size_t r) {
    return (r < 100000) || (r >= 200000 && r < 300000);
}
// rmap: 0 = identity, 1 = useful compact, 2 = non-useful compact
__device__ __forceinline__ size_t row_pos(int c, int rmap) {
    if (rmap == 0) return (size_t)c;
    if (rmap == 1) return (size_t)(c < 100000 ? c : c + 100000);
    return (size_t)(c < 100000 ? c + 100000 : c + 200000);
}

// ---------------- prologue kernels ----------------
__global__ void init_deg_kernel() {
    int i = blockIdx.x * blockDim.x + threadIdx.x;
    if (i < NN) g_deg[i] = 1.0f;
}
__global__ void count_deg_kernel(const int* __restrict__ ui, const int* __restrict__ ii) {
    int e = blockIdx.x * blockDim.x + threadIdx.x;
    if (e < BB) {
        atomicAdd(&g_deg[ii[e]], 1.0f);
        atomicAdd(&g_deg[ui[e] + BB], 1.0f);
    }
}
__global__ void scanA_kernel() {
    __shared__ int s[256];
    int t = threadIdx.x, b = blockIdx.x;
    int idx = b * 256 + t;
    int val = 0;
    if (idx < NCOMP) {
        int pos = idx < 100000 ? idx : idx + 100000;
        val = __float2int_rn(g_deg[pos]) - 1;
    }
    s[t] = val; __syncthreads();
#pragma unroll
    for (int d = 1; d < 256; d <<= 1) {
        int x = (t >= d) ? s[t - d] : 0;
        __syncthreads(); s[t] += x; __syncthreads();
    }
    if (idx < NCOMP) g_off[idx] = s[t] - val;
    if (t == 255) g_bsum[b] = s[255];
}
__global__ void scanB_kernel(int nb) {
    __shared__ int s[1024];
    int t = threadIdx.x;
    int val = (t < nb) ? g_bsum[t] : 0;
    s[t] = val; __syncthreads();
#pragma unroll
    for (int d = 1; d < 1024; d <<= 1) {
        int x = (t >= d) ? s[t - d] : 0;
        __syncthreads(); s[t] += x; __syncthreads();
    }
    if (t < nb) g_bsum[t] = s[t] - val;
}
__global__ void scanC_kernel() {
    int idx = blockIdx.x * 256 + threadIdx.x;
    if (idx < NCOMP) {
        int v = g_off[idx] + g_bsum[blockIdx.x];
        g_off[idx] = v;
        g_cur[idx] = v;
    }
    if (idx == 0) g_off[NCOMP] = NE;
}
__global__ void dinv_kernel() {
    int i = blockIdx.x * blockDim.x + threadIdx.x;
    if (i < NN) g_deg[i] = 1.0f / sqrtf(g_deg[i]);
}
__global__ void fill_edges_kernel(const int* __restrict__ ui, const int* __restrict__ ii) {
    int e = blockIdx.x * blockDim.x + threadIdx.x;
    if (e >= BB) return;
    int a  = ii[e];
    int up = ui[e] + BB;
    int cb = 100000 + ui[e];
    float norm = g_deg[a] * g_deg[up];
    int i1 = atomicAdd(&g_cur[a], 1);
    g_edge[i1] = make_int2(up, __float_as_int(norm));
    int i2 = atomicAdd(&g_cur[cb], 1);
    g_edge[i2] = make_int2(a, __float_as_int(norm));
}
__global__ void wprep_kernel(const float* __restrict__ Wall) {
    int idx = blockIdx.x * blockDim.x + threadIdx.x;
    if (idx >= 3 * 128 * 128) return;
    int l = idx / 16384, r = idx % 16384;
    int k = r / 128, n = r % 128;
    float v = Wall[l * 16384 + k * 128 + n];
    __nv_bfloat16 hi = __float2bfloat16(v);
    __nv_bfloat16 lo = __float2bfloat16(v - __bfloat162float(hi));
    uint32_t off = ((uint32_t)n * PITCH + (uint32_t)k) * 2;
    *(__nv_bfloat16*)(g_Wt_hi[l] + off) = hi;
    *(__nv_bfloat16*)(g_Wt_lo[l] + off) = lo;
}

// ---------------- GEMM body (R7/R11 shape) ----------------
#define SM_AHI   0
#define SM_ALO   (TM * PITCH * 2)               // 17408
#define SM_WHI   (2 * TM * PITCH * 2)           // 34816
#define SM_WLO   (SM_WHI + 128 * PITCH * 2)     // 69632
#define SM_BIAS  (SM_WLO + 128 * PITCH * 2)     // 104448
#define SM_BIAS2 (SM_BIAS + 512)                // 104960
#define SM_TOTAL (SM_BIAS2 + 512)               // 105472

// mode 0: A row pos = table gather (AGGin=user_table, IT=item_table), no act
// mode 1: A row pos = relu( (useful ? AGGin[pos] : Hall[pos]) + bprev )
// epilogue: writes Hout[pos]; if last && !useful(pos): relu(acc+bfin) -> outp
__device__ __forceinline__ void gemm_body(
    int cta, const float* __restrict__ AGGin, const float* __restrict__ Hall,
    const int* __restrict__ ui, const int* __restrict__ ii,
    const float* __restrict__ IT, int mode, int rmap,
    int layer, const float* __restrict__ bprev,
    float* __restrict__ Hout,
    float* __restrict__ outp, const float* __restrict__ bfin, int last,
    char* smem)
{
    uint32_t sb = smem_u32(smem);
    int tid = threadIdx.x, warp = tid >> 5, lane = tid & 31;
    int c0 = cta * TM;

    // async W tile copy (2176 uint4 each)
    {
        const uint4* wh = (const uint4*)g_Wt_hi[layer];
        const uint4* wl = (const uint4*)g_Wt_lo[layer];
        uint32_t dh = sb + SM_WHI, dl = sb + SM_WLO;
#pragma unroll
        for (int i = 0; i < 17; i++) {
            int idx = tid + i * NTHR;
            cp_async16(dh + idx * 16, wh + idx);
            cp_async16(dl + idx * 16, wl + idx);
        }
        asm volatile("cp.async.commit_group;" ::: "memory");
    }
    ((float*)(smem + SM_BIAS))[tid]  = mode ? bprev[tid] : 0.0f;
    ((float*)(smem + SM_BIAS2))[tid] = last ? bfin[tid] : 0.0f;
    __syncthreads();
    const float* bsm  = (const float*)(smem + SM_BIAS);
    const float* bsm2 = (const float*)(smem + SM_BIAS2);

    // A-phase
#pragma unroll
    for (int i = 0; i < 16; i++) {
        int row = warp * 16 + i;
        size_t p = row_pos(c0 + row, rmap);
        float4 v;
        if (mode == 0) {
            if (p < BB) v = ((const float4*)(AGGin + (size_t)ui[p] * DD))[lane];
            else        v = ((const float4*)(IT    + (size_t)ii[p - BB] * DD))[lane];
        } else {
            const float* src = h_useful(p) ? AGGin : Hall;
            v = ((const float4*)(src + p * DD))[lane];
            int cc = lane * 4;
            v.x = fmaxf(v.x + bsm[cc + 0], 0.0f);
            v.y = fmaxf(v.y + bsm[cc + 1], 0.0f);
            v.z = fmaxf(v.z + bsm[cc + 2], 0.0f);
            v.w = fmaxf(v.w + bsm[cc + 3], 0.0f);
        }
        __nv_bfloat16 h0 = __float2bfloat16(v.x), h1 = __float2bfloat16(v.y);
        __nv_bfloat16 h2 = __float2bfloat16(v.z), h3 = __float2bfloat16(v.w);
        __nv_bfloat16 l0 = __float2bfloat16(v.x - __bfloat162float(h0));
        __nv_bfloat16 l1 = __float2bfloat16(v.y - __bfloat162float(h1));
        __nv_bfloat16 l2 = __float2bfloat16(v.z - __bfloat162float(h2));
        __nv_bfloat16 l3 = __float2bfloat16(v.w - __bfloat162float(h3));
        uint2 hp, lp;
        hp.x = (uint32_t)__bfloat16_as_ushort(h0) | ((uint32_t)__bfloat16_as_ushort(h1) << 16);
        hp.y = (uint32_t)__bfloat16_as_ushort(h2) | ((uint32_t)__bfloat16_as_ushort(h3) << 16);
        lp.x = (uint32_t)__bfloat16_as_ushort(l0) | ((uint32_t)__bfloat16_as_ushort(l1) << 16);
        lp.y = (uint32_t)__bfloat16_as_ushort(l2) | ((uint32_t)__bfloat16_as_ushort(l3) << 16);
        uint32_t off = ((uint32_t)row * PITCH + (uint32_t)lane * 4) * 2;
        *(uint2*)(smem + SM_AHI + off) = hp;
        *(uint2*)(smem + SM_ALO + off) = lp;
    }
    asm volatile("cp.async.wait_group 0;" ::: "memory");
    __syncthreads();

    // mainloop
    int arow = warp * 16 + (lane & 15);
    uint32_t aoff = sb + SM_AHI + ((uint32_t)arow * PITCH + (uint32_t)((lane >> 4) * 8)) * 2;
    int brow = (lane & 7) + ((lane >> 4) & 1) * 8;
    uint32_t boff = sb + SM_WHI + ((uint32_t)brow * PITCH + (uint32_t)(((lane >> 3) & 1) * 8)) * 2;

    float acc[16][4];
#pragma unroll
    for (int i = 0; i < 16; i++) { acc[i][0] = acc[i][1] = acc[i][2] = acc[i][3] = 0.f; }

#pragma unroll
    for (int k = 0; k < 8; k++) {
        uint32_t ah[4], al[4];
        uint32_t ak = aoff + (uint32_t)k * 32;
        ldm_x4(ak, ah[0], ah[1], ah[2], ah[3]);
        ldm_x4(ak + (SM_ALO - SM_AHI), al[0], al[1], al[2], al[3]);
#pragma unroll
        for (int t = 0; t < 8; t++) {
            uint32_t bh0, bh1, bh2, bh3, bl0, bl1, bl2, bl3;
            uint32_t bk = boff + (uint32_t)t * (16 * PITCH * 2) + (uint32_t)k * 32;
            ldm_x4(bk,                     bh0, bh1, bh2, bh3);
            ldm_x4(bk + (SM_WLO - SM_WHI), bl0, bl1, bl2, bl3);
            mma_bf16(acc[2 * t + 0], ah, bh0, bh1);
            mma_bf16(acc[2 * t + 1], ah, bh2, bh3);
            mma_bf16(acc[2 * t + 0], al, bh0, bh1);
            mma_bf16(acc[2 * t + 1], al, bh2, bh3);
            mma_bf16(acc[2 * t + 0], ah, bl0, bl1);
            mma_bf16(acc[2 * t + 1], ah, bl2, bl3);
        }
    }

    // epilogue
    int grp = lane >> 2, qc = 2 * (lane & 3);
    size_t rA = row_pos(c0 + warp * 16 + grp, rmap);
    size_t rB = row_pos(c0 + warp * 16 + grp + 8, rmap);
    bool fA = last && !h_useful(rA);
    bool fB = last && !h_useful(rB);
    float* D0 = (fA ? outp : Hout) + rA * DD;
    float* D1 = (fB ? outp : Hout) + rB * DD;
#pragma unroll
    for (int nt = 0; nt < 16; nt++) {
        int col = nt * 8 + qc;
        float2 v0 = make_float2(acc[nt][0], acc[nt][1]);
        float2 v1 = make_float2(acc[nt][2], acc[nt][3]);
        if (fA) v0 = make_float2(fmaxf(v0.x + bsm2[col], 0.f), fmaxf(v0.y + bsm2[col + 1], 0.f));
        if (fB) v1 = make_float2(fmaxf(v1.x + bsm2[col], 0.f), fmaxf(v1.y + bsm2[col + 1], 0.f));
        *(float2*)(D0 + col) = v0;
        *(float2*)(D1 + col) = v1;
    }
}

// ---------------- pull body: 4 warps x 16 compact rows ----------------
__device__ __forceinline__ void pull_body(int cta, const float* __restrict__ Hin,
                                          const float* __restrict__ dinv,
                                          float* __restrict__ AGG)
{
    int warp = threadIdx.x >> 5, lane = threadIdx.x & 31;
    int cbase = cta * 64 + warp * 16;
#pragma unroll 1
    for (int i = 0; i < 16; i++) {
        int c = cbase + i;
        size_t p = (size_t)c + (c < 100000 ? 0 : 100000);
        float dv = dinv[p]; float d2 = dv * dv;
        float4 v = ((const float4*)(Hin + p * DD))[lane];
        v.x *= d2; v.y *= d2; v.z *= d2; v.w *= d2;
        int e0 = g_off[c], e1 = g_off[c + 1];
        for (int j = e0; j < e1; j++) {
            int2 en = g_edge[j];
            float nm = __int_as_float(en.y);
            float4 hv = ((const float4*)(Hin + (size_t)en.x * DD))[lane];
            v.x += nm * hv.x; v.y += nm * hv.y;
            v.z += nm * hv.z; v.w += nm * hv.w;
        }
        ((float4*)(AGG + p * DD))[lane] = v;
    }
}

// ---------------- kernels ----------------
__global__ void __launch_bounds__(NTHR, 2)
gemm_kernel(const float* __restrict__ AGGin, const float* __restrict__ Hall,
            const int* __restrict__ ui, const int* __restrict__ ii,
            const float* __restrict__ IT, int mode, int rmap,
            int layer, const float* __restrict__ bprev,
            float* __restrict__ Hout,
            float* __restrict__ outp, const float* __restrict__ bfin, int last)
{
    extern __shared__ char smem[];
    gemm_body(blockIdx.x, AGGin, Hall, ui, ii, IT, mode, rmap, layer, bprev,
              Hout, outp, bfin, last, smem);
}

// even blocks: gemm (3125 CTAs); odd blocks: pull (3125 CTAs)
__global__ void __launch_bounds__(NTHR, 2)
combo_kernel(const float* __restrict__ AGGin, const float* __restrict__ Hall,
             const int* __restrict__ ui, const int* __restrict__ ii,
             const float* __restrict__ IT, int mode, int rmap,
             int layer, const float* __restrict__ bprev,
             float* __restrict__ Hout,
             float* __restrict__ outp, const float* __restrict__ bfin, int last,
             const float* __restrict__ pHin, float* __restrict__ pAGG,
             const float* __restrict__ dinv)
{
    extern __shared__ char smem[];
    int b = blockIdx.x;
    if ((b & 1) == 0)
        gemm_body(b >> 1, AGGin, Hall, ui, ii, IT, mode, rmap, layer, bprev,
                  Hout, outp, bfin, last, smem);
    else
        pull_body(b >> 1, pHin, dinv, pAGG);
}

// final pull for useful rows: out = relu(d2*H[p] + sum norm*H[nbr] + b2)
__global__ void final_pull_kernel(const float* __restrict__ Hin,
                                  const float* __restrict__ dinv,
                                  const float* __restrict__ b2,
                                  float* __restrict__ out) {
    int t = blockIdx.x * blockDim.x + threadIdx.x;
    int c = t >> 5;
    if (c >= NCOMP) return;
    int lane = t & 31;
    size_t p = (size_t)c + (c < 100000 ? 0 : 100000);
    float dv = dinv[p]; float d2 = dv * dv;
    float4 v = ((const float4*)(Hin + p * DD))[lane];
    v.x *= d2; v.y *= d2; v.z *= d2; v.w *= d2;
    int e0 = g_off[c], e1 = g_off[c + 1];
    for (int j = e0; j < e1; j++) {
        int2 en = g_edge[j];
        float nm = __int_as_float(en.y);
        float4 hv = ((const float4*)(Hin + (size_t)en.x * DD))[lane];
        v.x += nm * hv.x; v.y += nm * hv.y;
        v.z += nm * hv.z; v.w += nm * hv.w;
    }
    float4 bb = ((const float4*)b2)[lane];
    v.x = fmaxf(v.x + bb.x, 0.0f);
    v.y = fmaxf(v.y + bb.y, 0.0f);
    v.z = fmaxf(v.z + bb.z, 0.0f);
    v.w = fmaxf(v.w + bb.w, 0.0f);
    ((float4*)(out + p * DD))[lane] = v;
}

extern "C" void kernel_launch(void* const* d_in, const int* in_sizes, int n_in,
                              void* d_out, int out_size) {
    const int*   ui   = (const int*)d_in[0];
    const int*   ii   = (const int*)d_in[1];
    const float* UT   = (const float*)d_in[2];
    const float* IT   = (const float*)d_in[3];
    const float* Wall = (const float*)d_in[4];
    const float* ball = (const float*)d_in[5];
    float* out = (float*)d_out;

    float *deg, *H, *P0, *P1;
    cudaGetSymbolAddress((void**)&deg, g_deg);
    cudaGetSymbolAddress((void**)&H,   g_H);
    cudaGetSymbolAddress((void**)&P0,  g_P0);
    cudaGetSymbolAddress((void**)&P1,  g_P1);

    cudaFuncSetAttribute(gemm_kernel,  cudaFuncAttributeMaxDynamicSharedMemorySize, SM_TOTAL);
    cudaFuncSetAttribute(combo_kernel, cudaFuncAttributeMaxDynamicSharedMemorySize, SM_TOTAL);

    const int NSCB = (NCOMP + 255) / 256;            // 782
    const int HB   = NCOMP / TM;                     // 3125 (half grid)
    const int PBLK = (NCOMP * 32 + 255) / 256;

    init_deg_kernel<<<(NN + 255) / 256, 256>>>();
    count_deg_kernel<<<(BB + 255) / 256, 256>>>(ui, ii);
    scanA_kernel<<<NSCB, 256>>>();
    scanB_kernel<<<1, 1024>>>(NSCB);
    scanC_kernel<<<NSCB, 256>>>();
    dinv_kernel<<<(NN + 255) / 256, 256>>>();
    fill_edges_kernel<<<(BB + 255) / 256, 256>>>(ui, ii);
    wprep_kernel<<<(3 * 128 * 128 + 255) / 256, 256>>>(Wall);

    // S1: layer-0 GEMM, useful rows -> H0_u in P0
    gemm_kernel<<<HB, NTHR, SM_TOTAL>>>(UT, nullptr, ui, ii, IT, 0, 1, 0, nullptr,
                                        P0, nullptr, nullptr, 0);
    // S2: layer-0 GEMM non-useful (-> P0)  ||  pull0 (P0 -> AGG0 in P1)
    combo_kernel<<<2 * HB, NTHR, SM_TOTAL>>>(UT, nullptr, ui, ii, IT, 0, 2, 0, nullptr,
                                             P0, nullptr, nullptr, 0,
                                             P0, P1, deg);
    // S3: layer-1 GEMM, all rows (useful from AGG0=P1, non-useful from H0=P0) -> H1 in g_H
    gemm_kernel<<<NN / TM, NTHR, SM_TOTAL>>>(P1, P0, ui, ii, nullptr, 1, 0, 1, ball,
                                             H, nullptr, nullptr, 0);
    // S4: layer-2 GEMM non-useful (finalize -> out)  ||  pull1 (g_H -> AGG1 in P0)
    combo_kernel<<<2 * HB, NTHR, SM_TOTAL>>>(H, H, ui, ii, nullptr, 1, 2, 2, ball + DD,
                                             P1, out, ball + 2 * DD, 1,
                                             H, P0, deg);
    // S5: layer-2 GEMM useful (A = relu(AGG1 + b1)) -> H2_u in P1
    gemm_kernel<<<HB, NTHR, SM_TOTAL>>>(P0, H, ui, ii, nullptr, 1, 1, 2, ball + DD,
                                        P1, nullptr, nullptr, 0);
    // S6: final pull for useful rows
    final_pull_kernel<<<PBLK, 256>>>(P1, deg, ball + 2 * DD, out);
}

// round 13
// speedup vs baseline: 1.6644x; 1.6644x over previous
#include <cuda_runtime.h>
#include <cuda_bf16.h>
#include <cstdint>

#define BB 200000      // batch size
#define NN 400000      // nodes = 2*BB
#define DD 128         // embedding dim
#define PITCH 136      // padded bf16 pitch for smem tiles
#define TM 64          // GEMM tile rows per CTA
#define NTHR 128       // threads per GEMM CTA (4 warps)
#define NCOMP 200000   // useful rows, compact: [0,100k) u [200k,300k)
#define NE (2 * BB)    // directed edges

// ---------------- scratch (device globals; no allocs allowed) ----------------
__device__ float g_deg[NN];                       // degree -> dinv (in place)
__device__ float g_H [(size_t)NN * DD];           // buffer C (H1)
__device__ float g_P0[(size_t)NN * DD];           // buffer A
__device__ float g_P1[(size_t)NN * DD];           // buffer B
__device__ uint4 g_Wfrag_hi[3 * 64 * 32];         // mma B fragments, hi (32KB/layer)
__device__ uint4 g_Wfrag_lo[3 * 64 * 32];         // mma B fragments, lo
__device__ int  g_off[NCOMP + 1];                 // CSR offsets (compact)
__device__ int  g_cur[NCOMP];                     // fill cursors
__device__ int  g_bsum[800];                      // scan block sums
__device__ int2 g_edge[NE];                       // (nbr position, norm bits)

// ---------------- helpers ----------------
__device__ __forceinline__ uint32_t smem_u32(const void* p) {
    uint32_t a;
    asm("{ .reg .u64 t; cvta.to.shared.u64 t, %1; cvt.u32.u64 %0, t; }" : "=r"(a) : "l"(p));
    return a;
}
__device__ __forceinline__ void ldm_x4(uint32_t a, uint32_t& r0, uint32_t& r1,
                                       uint32_t& r2, uint32_t& r3) {
    asm volatile("ldmatrix.sync.aligned.m8n8.x4.shared.b16 {%0,%1,%2,%3}, [%4];"
                 : "=r"(r0), "=r"(r1), "=r"(r2), "=r"(r3) : "r"(a));
}
__device__ __forceinline__ void mma_bf16(float* c, const uint32_t* a, uint32_t b0, uint32_t b1) {
    asm volatile("mma.sync.aligned.m16n8k16.row.col.f32.bf16.bf16.f32 "
                 "{%0,%1,%2,%3}, {%4,%5,%6,%7}, {%8,%9}, {%0,%1,%2,%3};"
                 : "+f"(c[0]), "+f"(c[1]), "+f"(c[2]), "+f"(c[3])
                 : "r"(a[0]), "r"(a[1]), "r"(a[2]), "r"(a[3]), "r"(b0), "r"(b1));
}
__device__ __forceinline__ bool h_useful(size_t r) {
    return (r < 100000) || (r >= 200000 && r < 300000);
}

// ---------------- prologue kernels ----------------
__global__ void init_deg_kernel() {
    int i = blockIdx.x * blockDim.x + threadIdx.x;
    if (i < NN) g_deg[i] = 1.0f;
}
__global__ void count_deg_kernel(const int* __restrict__ ui, const int* __restrict__ ii) {
    int e = blockIdx.x * blockDim.x + threadIdx.x;
    if (e < BB) {
        atomicAdd(&g_deg[ii[e]], 1.0f);
        atomicAdd(&g_deg[ui[e] + BB], 1.0f);
    }
}
__global__ void scanA_kernel() {
    __shared__ int s[256];
    int t = threadIdx.x, b = blockIdx.x;
    int idx = b * 256 + t;
    int val = 0;
    if (idx < NCOMP) {
        int pos = idx < 100000 ? idx : idx + 100000;
        val = __float2int_rn(g_deg[pos]) - 1;
    }
    s[t] = val; __syncthreads();
#pragma unroll
    for (int d = 1; d < 256; d <<= 1) {
        int x = (t >= d) ? s[t - d] : 0;
        __syncthreads(); s[t] += x; __syncthreads();
    }
    if (idx < NCOMP) g_off[idx] = s[t] - val;
    if (t == 255) g_bsum[b] = s[255];
}
__global__ void scanB_kernel(int nb) {
    __shared__ int s[1024];
    int t = threadIdx.x;
    int val = (t < nb) ? g_bsum[t] : 0;
    s[t] = val; __syncthreads();
#pragma unroll
    for (int d = 1; d < 1024; d <<= 1) {
        int x = (t >= d) ? s[t - d] : 0;
        __syncthreads(); s[t] += x; __syncthreads();
    }
    if (t < nb) g_bsum[t] = s[t] - val;
}
__global__ void scanC_kernel() {
    int idx = blockIdx.x * 256 + threadIdx.x;
    if (idx < NCOMP) {
        int v = g_off[idx] + g_bsum[blockIdx.x];
        g_off[idx] = v;
        g_cur[idx] = v;
    }
    if (idx == 0) g_off[NCOMP] = NE;
}
__global__ void dinv_kernel() {
    int i = blockIdx.x * blockDim.x + threadIdx.x;
    if (i < NN) g_deg[i] = 1.0f / sqrtf(g_deg[i]);
}
__global__ void fill_edges_kernel(const int* __restrict__ ui, const int* __restrict__ ii) {
    int e = blockIdx.x * blockDim.x + threadIdx.x;
    if (e >= BB) return;
    int a  = ii[e];
    int up = ui[e] + BB;
    int cb = 100000 + ui[e];
    float norm = g_deg[a] * g_deg[up];
    int i1 = atomicAdd(&g_cur[a], 1);
    g_edge[i1] = make_int2(up, __float_as_int(norm));
    int i2 = atomicAdd(&g_cur[cb], 1);
    g_edge[i2] = make_int2(a, __float_as_int(norm));
}

// Build mma B-operand fragments once per layer. One CTA per layer, 128 threads.
// Replays the EXACT smem layout + ldmatrix sequence the GEMM used in R11,
// so the fragment register mapping is identical by construction.
__global__ void wfrag_kernel(const float* __restrict__ Wall) {
    extern __shared__ char smem[];   // [0,34816) = Whi padded, [34816,69632) = Wlo
    int layer = blockIdx.x;
    int tid = threadIdx.x;
    for (int idx = tid; idx < 128 * 128; idx += 128) {
        int k = idx >> 7, n = idx & 127;
        float v = Wall[layer * 16384 + idx];           // W[k][n]
        __nv_bfloat16 hi = __float2bfloat16(v);
        __nv_bfloat16 lo = __float2bfloat16(v - __bfloat162float(hi));
        uint32_t off = ((uint32_t)n * PITCH + (uint32_t)k) * 2;   // Wt[n][k]
        *(__nv_bfloat16*)(smem + off)         = hi;
        *(__nv_bfloat16*)(smem + 34816 + off) = lo;
    }
    __syncthreads();
    uint32_t sb = smem_u32(smem);
    int warp = tid >> 5, lane = tid & 31;
    int brow = (lane & 7) + ((lane >> 4) & 1) * 8;
    uint32_t boff = sb + ((uint32_t)brow * PITCH + (uint32_t)(((lane >> 3) & 1) * 8)) * 2;
#pragma unroll
    for (int kk = 0; kk < 2; kk++) {
        int k = warp * 2 + kk;
#pragma unroll
        for (int t = 0; t < 8; t++) {
            uint32_t bk = boff + (uint32_t)t * (16 * PITCH * 2) + (uint32_t)k * 32;
            uint32_t h0, h1, h2, h3, l0, l1, l2, l3;
            ldm_x4(bk,         h0, h1, h2, h3);
            ldm_x4(bk + 34816, l0, l1, l2, l3);
            size_t fi = ((size_t)layer * 64 + (size_t)(k * 8 + t)) * 32 + lane;
            g_Wfrag_hi[fi] = make_uint4(h0, h1, h2, h3);
            g_Wfrag_lo[fi] = make_uint4(l0, l1, l2, l3);
        }
    }
}

// ---------------- HMMA GEMM: A in smem, W fragments via LDG (L1-resident) ----
#define SM_AHI   0
#define SM_ALO   (TM * PITCH * 2)               // 17408
#define SM_BIAS  (2 * TM * PITCH * 2)           // 34816
#define SM_BIAS2 (SM_BIAS + 512)                // 35328
#define SM_TOTAL (SM_BIAS2 + 512)               // 35840  -> 4+ CTAs/SM

// mode 0: A row p = table gather (AGGin=user_table, IT=item_table), no act
// mode 1: A row p = relu( (useful ? AGGin[p] : Hall[p]) + bprev )
// epilogue: writes Hout[p]; if last && !useful(p): relu(acc+bfin) -> outp
__global__ void __launch_bounds__(NTHR, 4)
tc_gemm_kernel(const float* __restrict__ AGGin, const float* __restrict__ Hall,
               const int* __restrict__ ui, const int* __restrict__ ii,
               const float* __restrict__ IT, int mode,
               int layer, const float* __restrict__ bprev,
               float* __restrict__ Hout,
               float* __restrict__ outp, const float* __restrict__ bfin, int last)
{
    extern __shared__ char smem[];
    uint32_t sb = smem_u32(smem);
    int tid = threadIdx.x, warp = tid >> 5, lane = tid & 31;
    size_t row0 = (size_t)blockIdx.x * TM;

    ((float*)(smem + SM_BIAS))[tid]  = mode ? bprev[tid] : 0.0f;
    ((float*)(smem + SM_BIAS2))[tid] = last ? bfin[tid] : 0.0f;
    __syncthreads();
    const float* bsm  = (const float*)(smem + SM_BIAS);
    const float* bsm2 = (const float*)(smem + SM_BIAS2);

    // A-phase: load, act, bf16 hi/lo split, store padded
#pragma unroll
    for (int i = 0; i < 16; i++) {
        int row = warp * 16 + i;
        size_t p = row0 + row;
        float4 v;
        if (mode == 0) {
            if (p < BB) v = ((const float4*)(AGGin + (size_t)ui[p] * DD))[lane];
            else        v = ((const float4*)(IT    + (size_t)ii[p - BB] * DD))[lane];
        } else {
            const float* src = h_useful(p) ? AGGin : Hall;
            v = ((const float4*)(src + p * DD))[lane];
            int cc = lane * 4;
            v.x = fmaxf(v.x + bsm[cc + 0], 0.0f);
            v.y = fmaxf(v.y + bsm[cc + 1], 0.0f);
            v.z = fmaxf(v.z + bsm[cc + 2], 0.0f);
            v.w = fmaxf(v.w + bsm[cc + 3], 0.0f);
        }
        __nv_bfloat16 h0 = __float2bfloat16(v.x), h1 = __float2bfloat16(v.y);
        __nv_bfloat16 h2 = __float2bfloat16(v.z), h3 = __float2bfloat16(v.w);
        __nv_bfloat16 l0 = __float2bfloat16(v.x - __bfloat162float(h0));
        __nv_bfloat16 l1 = __float2bfloat16(v.y - __bfloat162float(h1));
        __nv_bfloat16 l2 = __float2bfloat16(v.z - __bfloat162float(h2));
        __nv_bfloat16 l3 = __float2bfloat16(v.w - __bfloat162float(h3));
        uint2 hp, lp;
        hp.x = (uint32_t)__bfloat16_as_ushort(h0) | ((uint32_t)__bfloat16_as_ushort(h1) << 16);
        hp.y = (uint32_t)__bfloat16_as_ushort(h2) | ((uint32_t)__bfloat16_as_ushort(h3) << 16);
        lp.x = (uint32_t)__bfloat16_as_ushort(l0) | ((uint32_t)__bfloat16_as_ushort(l1) << 16);
        lp.y = (uint32_t)__bfloat16_as_ushort(l2) | ((uint32_t)__bfloat16_as_ushort(l3) << 16);
        uint32_t off = ((uint32_t)row * PITCH + (uint32_t)lane * 4) * 2;
        *(uint2*)(smem + SM_AHI + off) = hp;
        *(uint2*)(smem + SM_ALO + off) = lp;
    }
    __syncthreads();

    // mainloop: A via ldmatrix, W fragments via LDG.128 (L1/L2-resident 64KB/layer)
    int arow = warp * 16 + (lane & 15);
    uint32_t aoff = sb + SM_AHI + ((uint32_t)arow * PITCH + (uint32_t)((lane >> 4) * 8)) * 2;
    const uint4* __restrict__ wfh = &g_Wfrag_hi[(size_t)layer * 2048 + lane];
    const uint4* __restrict__ wfl = &g_Wfrag_lo[(size_t)layer * 2048 + lane];

    float acc[16][4];
#pragma unroll
    for (int i = 0; i < 16; i++) { acc[i][0] = acc[i][1] = acc[i][2] = acc[i][3] = 0.f; }

#pragma unroll
    for (int k = 0; k < 8; k++) {
        uint32_t ah[4], al[4];
        uint32_t ak = aoff + (uint32_t)k * 32;
        ldm_x4(ak, ah[0], ah[1], ah[2], ah[3]);
        ldm_x4(ak + (SM_ALO - SM_AHI), al[0], al[1], al[2], al[3]);
#pragma unroll
        for (int t = 0; t < 8; t++) {
            uint4 bh = wfh[(k * 8 + t) * 32];
            uint4 bl = wfl[(k * 8 + t) * 32];
            mma_bf16(acc[2 * t + 0], ah, bh.x, bh.y);
            mma_bf16(acc[2 * t + 1], ah, bh.z, bh.w);
            mma_bf16(acc[2 * t + 0], al, bh.x, bh.y);
            mma_bf16(acc[2 * t + 1], al, bh.z, bh.w);
            mma_bf16(acc[2 * t + 0], ah, bl.x, bl.y);
            mma_bf16(acc[2 * t + 1], ah, bl.z, bl.w);
        }
    }

    // epilogue
    int grp = lane >> 2, qc = 2 * (lane & 3);
    size_t rA = row0 + warp * 16 + grp;
    size_t rB = rA + 8;
    bool fA = last && !h_useful(rA);
    bool fB = last && !h_useful(rB);
    float* D0 = (fA ? outp : Hout) + rA * DD;
    float* D1 = (fB ? outp : Hout) + rB * DD;
#pragma unroll
    for (int nt = 0; nt < 16; nt++) {
        int col = nt * 8 + qc;
        float2 v0 = make_float2(acc[nt][0], acc[nt][1]);
        float2 v1 = make_float2(acc[nt][2], acc[nt][3]);
        if (fA) v0 = make_float2(fmaxf(v0.x + bsm2[col], 0.f), fmaxf(v0.y + bsm2[col + 1], 0.f));
        if (fB) v1 = make_float2(fmaxf(v1.x + bsm2[col], 0.f), fmaxf(v1.y + bsm2[col + 1], 0.f));
        *(float2*)(D0 + col) = v0;
        *(float2*)(D1 + col) = v1;
    }
}

// ---------------- pull aggregation (one warp per useful row) ----------------
__global__ void pull_kernel(const float* __restrict__ Hin,
                            const float* __restrict__ dinv,
                            float* __restrict__ AGG) {
    int t = blockIdx.x * blockDim.x + threadIdx.x;
    int c = t >> 5;
    if (c >= NCOMP) return;
    int lane = t & 31;
    size_t p = (size_t)c + (c < 100000 ? 0 : 100000);
    float dv = dinv[p]; float d2 = dv * dv;
    float4 v = ((const float4*)(Hin + p * DD))[lane];
    v.x *= d2; v.y *= d2; v.z *= d2; v.w *= d2;
    int e0 = g_off[c], e1 = g_off[c + 1];
    for (int j = e0; j < e1; j++) {
        int2 en = g_edge[j];
        float nm = __int_as_float(en.y);
        float4 hv = ((const float4*)(Hin + (size_t)en.x * DD))[lane];
        v.x += nm * hv.x; v.y += nm * hv.y;
        v.z += nm * hv.z; v.w += nm * hv.w;
    }
    ((float4*)(AGG + p * DD))[lane] = v;
}

// final pull for useful rows: out = relu(d2*H[p] + sum norm*H[nbr] + b2)
__global__ void final_pull_kernel(const float* __restrict__ Hin,
                                  const float* __restrict__ dinv,
                                  const float* __restrict__ b2,
                                  float* __restrict__ out) {
    int t = blockIdx.x * blockDim.x + threadIdx.x;
    int c = t >> 5;
    if (c >= NCOMP) return;
    int lane = t & 31;
    size_t p = (size_t)c + (c < 100000 ? 0 : 100000);
    float dv = dinv[p]; float d2 = dv * dv;
    float4 v = ((const float4*)(Hin + p * DD))[lane];
    v.x *= d2; v.y *= d2; v.z *= d2; v.w *= d2;
    int e0 = g_off[c], e1 = g_off[c + 1];
    for (int j = e0; j < e1; j++) {
        int2 en = g_edge[j];
        float nm = __int_as_float(en.y);
        float4 hv = ((const float4*)(Hin + (size_t)en.x * DD))[lane];
        v.x += nm * hv.x; v.y += nm * hv.y;
        v.z += nm * hv.z; v.w += nm * hv.w;
    }
    float4 bb = ((const float4*)b2)[lane];
    v.x = fmaxf(v.x + bb.x, 0.0f);
    v.y = fmaxf(v.y + bb.y, 0.0f);
    v.z = fmaxf(v.z + bb.z, 0.0f);
    v.w = fmaxf(v.w + bb.w, 0.0f);
    ((float4*)(out + p * DD))[lane] = v;
}

extern "C" void kernel_launch(void* const* d_in, const int* in_sizes, int n_in,
                              void* d_out, int out_size) {
    const int*   ui   = (const int*)d_in[0];
    const int*   ii   = (const int*)d_in[1];
    const float* UT   = (const float*)d_in[2];
    const float* IT   = (const float*)d_in[3];
    const float* Wall = (const float*)d_in[4];
    const float* ball = (const float*)d_in[5];
    float* out = (float*)d_out;

    float *deg, *H, *P0, *P1;
    cudaGetSymbolAddress((void**)&deg, g_deg);
    cudaGetSymbolAddress((void**)&H,   g_H);
    cudaGetSymbolAddress((void**)&P0,  g_P0);
    cudaGetSymbolAddress((void**)&P1,  g_P1);

    cudaFuncSetAttribute(tc_gemm_kernel, cudaFuncAttributeMaxDynamicSharedMemorySize, SM_TOTAL);
    cudaFuncSetAttribute(wfrag_kernel,   cudaFuncAttributeMaxDynamicSharedMemorySize, 69632);

    const int NSCB = (NCOMP + 255) / 256;   // 782
    const int PBLK = (NCOMP * 32 + 255) / 256;

    init_deg_kernel<<<(NN + 255) / 256, 256>>>();
    count_deg_kernel<<<(BB + 255) / 256, 256>>>(ui, ii);
    scanA_kernel<<<NSCB, 256>>>();
    scanB_kernel<<<1, 1024>>>(NSCB);
    scanC_kernel<<<NSCB, 256>>>();
    dinv_kernel<<<(NN + 255) / 256, 256>>>();
    fill_edges_kernel<<<(BB + 255) / 256, 256>>>(ui, ii);
    wfrag_kernel<<<3, 128, 69632>>>(Wall);

    // layer 0: table gather -> H0 in P0
    tc_gemm_kernel<<<NN / TM, NTHR, SM_TOTAL>>>(UT, nullptr, ui, ii, IT, 0, 0, nullptr,
                                                P0, nullptr, nullptr, 0);
    pull_kernel<<<PBLK, 256>>>(P0, deg, P1);           // AGG0 (useful) in P1
    // layer 1: useful from P1, non-useful from P0 -> H1 in g_H
    tc_gemm_kernel<<<NN / TM, NTHR, SM_TOTAL>>>(P1, P0, ui, ii, nullptr, 1, 1, ball,
                                                H, nullptr, nullptr, 0);
    pull_kernel<<<PBLK, 256>>>(H, deg, P0);            // AGG1 (useful) in P0
    // layer 2: useful from P0, non-useful from g_H -> H2 in P1 (+ non-useful final out)
    tc_gemm_kernel<<<NN / TM, NTHR, SM_TOTAL>>>(P0, H, ui, ii, nullptr, 1, 2, ball + DD,
                                                P1, out, ball + 2 * DD, 1);
    // final: useful rows aggregate + bias + relu
    final_pull_kernel<<<PBLK, 256>>>(P1, deg, ball + 2 * DD, out);
}

// round 14
// speedup vs baseline: 1.7082x; 1.0264x over previous
#include <cuda_runtime.h>
#include <cuda_bf16.h>
#include <cstdint>

#define BB 200000      // batch size
#define NN 400000      // nodes = 2*BB
#define DD 128         // embedding dim
#define PITCH 136      // padded bf16 pitch for smem tiles
#define TM 64          // GEMM tile rows per CTA
#define NTHR 128       // threads per GEMM CTA (4 warps)
#define NCOMP 200000   // useful rows, compact: [0,100k) u [200k,300k)
#define NE (2 * BB)    // directed edges

// ---------------- scratch (device globals; no allocs allowed) ----------------
__device__ float g_deg[NN];                       // degree -> dinv (in place)
__device__ float g_H [(size_t)NN * DD];           // buffer C
__device__ float g_P0[(size_t)NN * DD];           // buffer A
__device__ float g_P1[(size_t)NN * DD];           // buffer B
__device__ uint4 g_Wfrag_hi[3 * 64 * 32];         // mma B fragments, hi (32KB/layer)
__device__ uint4 g_Wfrag_lo[3 * 64 * 32];         // mma B fragments, lo
__device__ int  g_off[NCOMP + 1];                 // CSR offsets (compact)
__device__ int  g_cur[NCOMP];                     // fill cursors
__device__ int  g_bsum[800];                      // scan block sums
__device__ int2 g_edge[NE];                       // (nbr position, norm bits)

// ---------------- helpers ----------------
__device__ __forceinline__ uint32_t smem_u32(const void* p) {
    uint32_t a;
    asm("{ .reg .u64 t; cvta.to.shared.u64 t, %1; cvt.u32.u64 %0, t; }" : "=r"(a) : "l"(p));
    return a;
}
__device__ __forceinline__ void ldm_x4(uint32_t a, uint32_t& r0, uint32_t& r1,
                                       uint32_t& r2, uint32_t& r3) {
    asm volatile("ldmatrix.sync.aligned.m8n8.x4.shared.b16 {%0,%1,%2,%3}, [%4];"
                 : "=r"(r0), "=r"(r1), "=r"(r2), "=r"(r3) : "r"(a));
}
__device__ __forceinline__ void mma_bf16(float* c, const uint32_t* a, uint32_t b0, uint32_t b1) {
    asm volatile("mma.sync.aligned.m16n8k16.row.col.f32.bf16.bf16.f32 "
                 "{%0,%1,%2,%3}, {%4,%5,%6,%7}, {%8,%9}, {%0,%1,%2,%3};"
                 : "+f"(c[0]), "+f"(c[1]), "+f"(c[2]), "+f"(c[3])
                 : "r"(a[0]), "r"(a[1]), "r"(a[2]), "r"(a[3]), "r"(b0), "r"(b1));
}
// pack two floats into bf16 hi and lo words
__device__ __forceinline__ uint32_t pack_hi2(float a, float b, uint32_t& lo) {
    __nv_bfloat16 h0 = __float2bfloat16(a), h1 = __float2bfloat16(b);
    __nv_bfloat16 l0 = __float2bfloat16(a - __bfloat162float(h0));
    __nv_bfloat16 l1 = __float2bfloat16(b - __bfloat162float(h1));
    lo = (uint32_t)__bfloat16_as_ushort(l0) | ((uint32_t)__bfloat16_as_ushort(l1) << 16);
    return (uint32_t)__bfloat16_as_ushort(h0) | ((uint32_t)__bfloat16_as_ushort(h1) << 16);
}

// ---------------- prologue kernels ----------------
__global__ void init_deg_kernel() {
    int i = blockIdx.x * blockDim.x + threadIdx.x;
    if (i < NN) g_deg[i] = 1.0f;
}
__global__ void count_deg_kernel(const int* __restrict__ ui, const int* __restrict__ ii) {
    int e = blockIdx.x * blockDim.x + threadIdx.x;
    if (e < BB) {
        atomicAdd(&g_deg[ii[e]], 1.0f);
        atomicAdd(&g_deg[ui[e] + BB], 1.0f);
    }
}
__global__ void scanA_kernel() {
    __shared__ int s[256];
    int t = threadIdx.x, b = blockIdx.x;
    int idx = b * 256 + t;
    int val = 0;
    if (idx < NCOMP) {
        int pos = idx < 100000 ? idx : idx + 100000;
        val = __float2int_rn(g_deg[pos]) - 1;
    }
    s[t] = val; __syncthreads();
#pragma unroll
    for (int d = 1; d < 256; d <<= 1) {
        int x = (t >= d) ? s[t - d] : 0;
        __syncthreads(); s[t] += x; __syncthreads();
    }
    if (idx < NCOMP) g_off[idx] = s[t] - val;
    if (t == 255) g_bsum[b] = s[255];
}
__global__ void scanB_kernel(int nb) {
    __shared__ int s[1024];
    int t = threadIdx.x;
    int val = (t < nb) ? g_bsum[t] : 0;
    s[t] = val; __syncthreads();
#pragma unroll
    for (int d = 1; d < 1024; d <<= 1) {
        int x = (t >= d) ? s[t - d] : 0;
        __syncthreads(); s[t] += x; __syncthreads();
    }
    if (t < nb) g_bsum[t] = s[t] - val;
}
__global__ void scanC_kernel() {
    int idx = blockIdx.x * 256 + threadIdx.x;
    if (idx < NCOMP) {
        int v = g_off[idx] + g_bsum[blockIdx.x];
        g_off[idx] = v;
        g_cur[idx] = v;
    }
    if (idx == 0) g_off[NCOMP] = NE;
}
__global__ void dinv_kernel() {
    int i = blockIdx.x * blockDim.x + threadIdx.x;
    if (i < NN) g_deg[i] = 1.0f / sqrtf(g_deg[i]);
}
__global__ void fill_edges_kernel(const int* __restrict__ ui, const int* __restrict__ ii) {
    int e = blockIdx.x * blockDim.x + threadIdx.x;
    if (e >= BB) return;
    int a  = ii[e];
    int up = ui[e] + BB;
    int cb = 100000 + ui[e];
    float norm = g_deg[a] * g_deg[up];
    int i1 = atomicAdd(&g_cur[a], 1);
    g_edge[i1] = make_int2(up, __float_as_int(norm));
    int i2 = atomicAdd(&g_cur[cb], 1);
    g_edge[i2] = make_int2(a, __float_as_int(norm));
}

// Build mma B-operand fragments once per layer (1 CTA/layer; replays GEMM layout)
__global__ void wfrag_kernel(const float* __restrict__ Wall) {
    extern __shared__ char smem[];   // [0,34816) Whi padded, [34816,69632) Wlo
    int layer = blockIdx.x;
    int tid = threadIdx.x;
    for (int idx = tid; idx < 128 * 128; idx += 128) {
        int k = idx >> 7, n = idx & 127;
        float v = Wall[layer * 16384 + idx];
        __nv_bfloat16 hi = __float2bfloat16(v);
        __nv_bfloat16 lo = __float2bfloat16(v - __bfloat162float(hi));
        uint32_t off = ((uint32_t)n * PITCH + (uint32_t)k) * 2;
        *(__nv_bfloat16*)(smem + off)         = hi;
        *(__nv_bfloat16*)(smem + 34816 + off) = lo;
    }
    __syncthreads();
    uint32_t sb = smem_u32(smem);
    int warp = tid >> 5, lane = tid & 31;
    int brow = (lane & 7) + ((lane >> 4) & 1) * 8;
    uint32_t boff = sb + ((uint32_t)brow * PITCH + (uint32_t)(((lane >> 3) & 1) * 8)) * 2;
#pragma unroll
    for (int kk = 0; kk < 2; kk++) {
        int k = warp * 2 + kk;
#pragma unroll
        for (int t = 0; t < 8; t++) {
            uint32_t bk = boff + (uint32_t)t * (16 * PITCH * 2) + (uint32_t)k * 32;
            uint32_t h0, h1, h2, h3, l0, l1, l2, l3;
            ldm_x4(bk,         h0, h1, h2, h3);
            ldm_x4(bk + 34816, l0, l1, l2, l3);
            size_t fi = ((size_t)layer * 64 + (size_t)(k * 8 + t)) * 32 + lane;
            g_Wfrag_hi[fi] = make_uint4(h0, h1, h2, h3);
            g_Wfrag_lo[fi] = make_uint4(l0, l1, l2, l3);
        }
    }
}

// ---------------- shared GEMM mainloop macro pieces ----------------
#define SM_AHI   0
#define SM_ALO   (TM * PITCH * 2)               // 17408
#define SM_BIAS  (2 * TM * PITCH * 2)           // 34816
#define SM_TOTAL_G (SM_BIAS + 512)              // 35328 (useful gemm)
#define SM_TOTAL_P (SM_BIAS + 1536)             // 36352 (passive: 3 biases)

__device__ __forceinline__ void mainloop(uint32_t sb, int warp, int lane, int layer,
                                         float acc[16][4]) {
    int arow = warp * 16 + (lane & 15);
    uint32_t aoff = sb + SM_AHI + ((uint32_t)arow * PITCH + (uint32_t)((lane >> 4) * 8)) * 2;
    const uint4* __restrict__ wfh = &g_Wfrag_hi[(size_t)layer * 2048 + lane];
    const uint4* __restrict__ wfl = &g_Wfrag_lo[(size_t)layer * 2048 + lane];
#pragma unroll
    for (int i = 0; i < 16; i++) { acc[i][0] = acc[i][1] = acc[i][2] = acc[i][3] = 0.f; }
#pragma unroll
    for (int k = 0; k < 8; k++) {
        uint32_t ah[4], al[4];
        uint32_t ak = aoff + (uint32_t)k * 32;
        ldm_x4(ak, ah[0], ah[1], ah[2], ah[3]);
        ldm_x4(ak + (SM_ALO - SM_AHI), al[0], al[1], al[2], al[3]);
#pragma unroll
        for (int t = 0; t < 8; t++) {
            uint4 bh = wfh[(k * 8 + t) * 32];
            uint4 bl = wfl[(k * 8 + t) * 32];
            mma_bf16(acc[2 * t + 0], ah, bh.x, bh.y);
            mma_bf16(acc[2 * t + 1], ah, bh.z, bh.w);
            mma_bf16(acc[2 * t + 0], al, bh.x, bh.y);
            mma_bf16(acc[2 * t + 1], al, bh.z, bh.w);
            mma_bf16(acc[2 * t + 0], ah, bl.x, bl.y);
            mma_bf16(acc[2 * t + 1], ah, bl.z, bl.w);
        }
    }
}

// ---------------- PASSIVE fused 3-layer chain (non-useful rows) ----------------
// rows: compact c -> position p = c<100k ? c+100k : c+200k (deg=1 throughout)
__global__ void __launch_bounds__(NTHR, 4)
passive_kernel(const float* __restrict__ UT, const float* __restrict__ IT,
               const int* __restrict__ ui, const int* __restrict__ ii,
               const float* __restrict__ ball, float* __restrict__ out)
{
    extern __shared__ char smem[];
    uint32_t sb = smem_u32(smem);
    int tid = threadIdx.x, warp = tid >> 5, lane = tid & 31;
    int c0 = blockIdx.x * TM;

    if (tid < 128) {
        ((float*)(smem + SM_BIAS))[tid]       = ball[tid];
        ((float*)(smem + SM_BIAS))[128 + tid] = ball[128 + tid];
        ((float*)(smem + SM_BIAS))[256 + tid] = ball[256 + tid];
    }
    __syncthreads();
    const float* bias = (const float*)(smem + SM_BIAS);

    // gather + split
#pragma unroll
    for (int i = 0; i < 16; i++) {
        int row = warp * 16 + i;
        int c = c0 + row;
        size_t p = (size_t)c + (c < 100000 ? 100000 : 200000);
        float4 v;
        if (p < BB) v = ((const float4*)(UT + (size_t)ui[p] * DD))[lane];
        else        v = ((const float4*)(IT + (size_t)ii[p - BB] * DD))[lane];
        uint2 hp, lp;
        hp.x = pack_hi2(v.x, v.y, lp.x);
        hp.y = pack_hi2(v.z, v.w, lp.y);
        uint32_t off = ((uint32_t)row * PITCH + (uint32_t)lane * 4) * 2;
        *(uint2*)(smem + SM_AHI + off) = hp;
        *(uint2*)(smem + SM_ALO + off) = lp;
    }
    __syncthreads();

    int grp = lane >> 2, qc = 2 * (lane & 3);
    float acc[16][4];
#pragma unroll 1
    for (int stage = 0; stage < 3; stage++) {
        mainloop(sb, warp, lane, stage, acc);
        if (stage < 2) {
            // relu(acc + b[stage]) -> re-split into A tile (warp-local rows)
            __syncwarp();
#pragma unroll
            for (int nt = 0; nt < 16; nt++) {
                int col = nt * 8 + qc;
                float bx = bias[stage * 128 + col], by = bias[stage * 128 + col + 1];
                float v0 = fmaxf(acc[nt][0] + bx, 0.f), v1 = fmaxf(acc[nt][1] + by, 0.f);
                float v2 = fmaxf(acc[nt][2] + bx, 0.f), v3 = fmaxf(acc[nt][3] + by, 0.f);
                int rAl = warp * 16 + grp, rBl = rAl + 8;
                uint32_t loA, loB;
                uint32_t hiA = pack_hi2(v0, v1, loA);
                uint32_t hiB = pack_hi2(v2, v3, loB);
                uint32_t offA = ((uint32_t)rAl * PITCH + (uint32_t)col) * 2;
                uint32_t offB = ((uint32_t)rBl * PITCH + (uint32_t)col) * 2;
                *(uint32_t*)(smem + SM_AHI + offA) = hiA;
                *(uint32_t*)(smem + SM_ALO + offA) = loA;
                *(uint32_t*)(smem + SM_AHI + offB) = hiB;
                *(uint32_t*)(smem + SM_ALO + offB) = loB;
            }
            __syncwarp();
        } else {
            // final: relu(acc + b2) -> out
            int cA = c0 + warp * 16 + grp, cB = cA + 8;
            size_t pA = (size_t)cA + (cA < 100000 ? 100000 : 200000);
            size_t pB = (size_t)cB + (cB < 100000 ? 100000 : 200000);
            float* oA = out + pA * DD;
            float* oB = out + pB * DD;
#pragma unroll
            for (int nt = 0; nt < 16; nt++) {
                int col = nt * 8 + qc;
                float bx = bias[256 + col], by = bias[256 + col + 1];
                *(float2*)(oA + col) =
                    make_float2(fmaxf(acc[nt][0] + bx, 0.f), fmaxf(acc[nt][1] + by, 0.f));
                *(float2*)(oB + col) =
                    make_float2(fmaxf(acc[nt][2] + bx, 0.f), fmaxf(acc[nt][3] + by, 0.f));
            }
        }
    }
}

// ---------------- USEFUL-rows GEMM (compact grid, 3125 CTAs) ----------------
// mode 0: A = table gather; mode 1: A = relu(AGGin[p] + bprev)
__global__ void __launch_bounds__(NTHR, 4)
gemm_u_kernel(const float* __restrict__ AGGin,
              const int* __restrict__ ui, const int* __restrict__ ii,
              const float* __restrict__ IT, int mode,
              int layer, const float* __restrict__ bprev,
              float* __restrict__ Hout)
{
    extern __shared__ char smem[];
    uint32_t sb = smem_u32(smem);
    int tid = threadIdx.x, warp = tid >> 5, lane = tid & 31;
    int c0 = blockIdx.x * TM;

    ((float*)(smem + SM_BIAS))[tid] = mode ? bprev[tid] : 0.0f;
    __syncthreads();
    const float* bsm = (const float*)(smem + SM_BIAS);

#pragma unroll
    for (int i = 0; i < 16; i++) {
        int row = warp * 16 + i;
        int c = c0 + row;
        size_t p = (size_t)c + (c < 100000 ? 0 : 100000);
        float4 v;
        if (mode == 0) {
            if (p < BB) v = ((const float4*)(AGGin + (size_t)ui[p] * DD))[lane];
            else        v = ((const float4*)(IT    + (size_t)ii[p - BB] * DD))[lane];
        } else {
            v = ((const float4*)(AGGin + p * DD))[lane];
            int cc = lane * 4;
            v.x = fmaxf(v.x + bsm[cc + 0], 0.0f);
            v.y = fmaxf(v.y + bsm[cc + 1], 0.0f);
            v.z = fmaxf(v.z + bsm[cc + 2], 0.0f);
            v.w = fmaxf(v.w + bsm[cc + 3], 0.0f);
        }
        uint2 hp, lp;
        hp.x = pack_hi2(v.x, v.y, lp.x);
        hp.y = pack_hi2(v.z, v.w, lp.y);
        uint32_t off = ((uint32_t)row * PITCH + (uint32_t)lane * 4) * 2;
        *(uint2*)(smem + SM_AHI + off) = hp;
        *(uint2*)(smem + SM_ALO + off) = lp;
    }
    __syncthreads();

    float acc[16][4];
    mainloop(sb, warp, lane, layer, acc);

    int grp = lane >> 2, qc = 2 * (lane & 3);
    int cA = c0 + warp * 16 + grp, cB = cA + 8;
    size_t pA = (size_t)cA + (cA < 100000 ? 0 : 100000);
    size_t pB = (size_t)cB + (cB < 100000 ? 0 : 100000);
    float* D0 = Hout + pA * DD;
    float* D1 = Hout + pB * DD;
#pragma unroll
    for (int nt = 0; nt < 16; nt++) {
        int col = nt * 8 + qc;
        *(float2*)(D0 + col) = make_float2(acc[nt][0], acc[nt][1]);
        *(float2*)(D1 + col) = make_float2(acc[nt][2], acc[nt][3]);
    }
}

// ---------------- pull aggregation (one warp per useful row) ----------------
__global__ void pull_kernel(const float* __restrict__ Hin,
                            const float* __restrict__ dinv,
                            float* __restrict__ AGG) {
    int t = blockIdx.x * blockDim.x + threadIdx.x;
    int c = t >> 5;
    if (c >= NCOMP) return;
    int lane = t & 31;
    size_t p = (size_t)c + (c < 100000 ? 0 : 100000);
    float dv = dinv[p]; float d2 = dv * dv;
    float4 v = ((const float4*)(Hin + p * DD))[lane];
    v.x *= d2; v.y *= d2; v.z *= d2; v.w *= d2;
    int e0 = g_off[c], e1 = g_off[c + 1];
    for (int j = e0; j < e1; j++) {
        int2 en = g_edge[j];
        float nm = __int_as_float(en.y);
        float4 hv = ((const float4*)(Hin + (size_t)en.x * DD))[lane];
        v.x += nm * hv.x; v.y += nm * hv.y;
        v.z += nm * hv.z; v.w += nm * hv.w;
    }
    ((float4*)(AGG + p * DD))[lane] = v;
}

// final pull for useful rows: out = relu(d2*H[p] + sum norm*H[nbr] + b2)
__global__ void final_pull_kernel(const float* __restrict__ Hin,
                                  const float* __restrict__ dinv,
                                  const float* __restrict__ b2,
                                  float* __restrict__ out) {
    int t = blockIdx.x * blockDim.x + threadIdx.x;
    int c = t >> 5;
    if (c >= NCOMP) return;
    int lane = t & 31;
    size_t p = (size_t)c + (c < 100000 ? 0 : 100000);
    float dv = dinv[p]; float d2 = dv * dv;
    float4 v = ((const float4*)(Hin + p * DD))[lane];
    v.x *= d2; v.y *= d2; v.z *= d2; v.w *= d2;
    int e0 = g_off[c], e1 = g_off[c + 1];
    for (int j = e0; j < e1; j++) {
        int2 en = g_edge[j];
        float nm = __int_as_float(en.y);
        float4 hv = ((const float4*)(Hin + (size_t)en.x * DD))[lane];
        v.x += nm * hv.x; v.y += nm * hv.y;
        v.z += nm * hv.z; v.w += nm * hv.w;
    }
    float4 bb = ((const float4*)b2)[lane];
    v.x = fmaxf(v.x + bb.x, 0.0f);
    v.y = fmaxf(v.y + bb.y, 0.0f);
    v.z = fmaxf(v.z + bb.z, 0.0f);
    v.w = fmaxf(v.w + bb.w, 0.0f);
    ((float4*)(out + p * DD))[lane] = v;
}

extern "C" void kernel_launch(void* const* d_in, const int* in_sizes, int n_in,
                              void* d_out, int out_size) {
    const int*   ui   = (const int*)d_in[0];
    const int*   ii   = (const int*)d_in[1];
    const float* UT   = (const float*)d_in[2];
    const float* IT   = (const float*)d_in[3];
    const float* Wall = (const float*)d_in[4];
    const float* ball = (const float*)d_in[5];
    float* out = (float*)d_out;

    float *deg, *H, *P0, *P1;
    cudaGetSymbolAddress((void**)&deg, g_deg);
    cudaGetSymbolAddress((void**)&H,   g_H);
    cudaGetSymbolAddress((void**)&P0,  g_P0);
    cudaGetSymbolAddress((void**)&P1,  g_P1);

    cudaFuncSetAttribute(gemm_u_kernel,  cudaFuncAttributeMaxDynamicSharedMemorySize, SM_TOTAL_G);
    cudaFuncSetAttribute(passive_kernel, cudaFuncAttributeMaxDynamicSharedMemorySize, SM_TOTAL_P);
    cudaFuncSetAttribute(wfrag_kernel,   cudaFuncAttributeMaxDynamicSharedMemorySize, 69632);

    const int NSCB = (NCOMP + 255) / 256;   // 782
    const int PBLK = (NCOMP * 32 + 255) / 256;
    const int GB   = NCOMP / TM;            // 3125

    init_deg_kernel<<<(NN + 255) / 256, 256>>>();
    count_deg_kernel<<<(BB + 255) / 256, 256>>>(ui, ii);
    scanA_kernel<<<NSCB, 256>>>();
    scanB_kernel<<<1, 1024>>>(NSCB);
    scanC_kernel<<<NSCB, 256>>>();
    dinv_kernel<<<(NN + 255) / 256, 256>>>();
    fill_edges_kernel<<<(BB + 255) / 256, 256>>>(ui, ii);
    wfrag_kernel<<<3, 128, 69632>>>(Wall);

    // passive half: fused 3-layer chain straight to out
    passive_kernel<<<GB, NTHR, SM_TOTAL_P>>>(UT, IT, ui, ii, ball, out);

    // useful half: (GEMM -> pull) x3
    gemm_u_kernel<<<GB, NTHR, SM_TOTAL_G>>>(UT, ui, ii, IT, 0, 0, nullptr, P0);
    pull_kernel<<<PBLK, 256>>>(P0, deg, P1);
    gemm_u_kernel<<<GB, NTHR, SM_TOTAL_G>>>(P1, ui, ii, nullptr, 1, 1, ball, H);
    pull_kernel<<<PBLK, 256>>>(H, deg, P0);
    gemm_u_kernel<<<GB, NTHR, SM_TOTAL_G>>>(P0, ui, ii, nullptr, 1, 2, ball + DD, P1);
    final_pull_kernel<<<PBLK, 256>>>(P1, deg, ball + 2 * DD, out);
}

// round 15
// speedup vs baseline: 1.7464x; 1.0223x over previous
#include <cuda_runtime.h>
#include <cuda_bf16.h>
#include <cstdint>

#define BB 200000      // batch size
#define NN 400000      // nodes = 2*BB
#define DD 128         // embedding dim
#define PITCH 136      // padded bf16 pitch for smem tiles
#define TM 64          // GEMM tile rows per CTA
#define NTHR 128       // threads per GEMM CTA (4 warps)
#define NCOMP 200000   // useful rows, compact: [0,100k) u [200k,300k)
#define NE (2 * BB)    // directed edges

// ---------------- scratch (device globals; no allocs allowed) ----------------
__device__ float g_deg[NN];                       // degree -> dinv (in place)
__device__ float g_H [(size_t)NN * DD];           // buffer C
__device__ float g_P0[(size_t)NN * DD];           // buffer A
__device__ float g_P1[(size_t)NN * DD];           // buffer B
__device__ uint4 g_Wfrag_hi[3 * 64 * 32];         // mma B fragments, hi (32KB/layer)
__device__ uint4 g_Wfrag_lo[3 * 64 * 32];         // mma B fragments, lo
__device__ int  g_off[NCOMP + 1];                 // CSR offsets (compact)
__device__ int  g_cur[NCOMP];                     // fill cursors
__device__ int  g_bsum[800];                      // scan block sums
__device__ int2 g_edge[NE];                       // (nbr position, norm bits)

// ---------------- helpers ----------------
__device__ __forceinline__ uint32_t smem_u32(const void* p) {
    uint32_t a;
    asm("{ .reg .u64 t; cvta.to.shared.u64 t, %1; cvt.u32.u64 %0, t; }" : "=r"(a) : "l"(p));
    return a;
}
__device__ __forceinline__ void ldm_x4(uint32_t a, uint32_t& r0, uint32_t& r1,
                                       uint32_t& r2, uint32_t& r3) {
    asm volatile("ldmatrix.sync.aligned.m8n8.x4.shared.b16 {%0,%1,%2,%3}, [%4];"
                 : "=r"(r0), "=r"(r1), "=r"(r2), "=r"(r3) : "r"(a));
}
__device__ __forceinline__ void mma_bf16(float* c, const uint32_t* a, uint32_t b0, uint32_t b1) {
    asm volatile("mma.sync.aligned.m16n8k16.row.col.f32.bf16.bf16.f32 "
                 "{%0,%1,%2,%3}, {%4,%5,%6,%7}, {%8,%9}, {%0,%1,%2,%3};"
                 : "+f"(c[0]), "+f"(c[1]), "+f"(c[2]), "+f"(c[3])
                 : "r"(a[0]), "r"(a[1]), "r"(a[2]), "r"(a[3]), "r"(b0), "r"(b1));
}
__device__ __forceinline__ uint32_t pack_hi2(float a, float b, uint32_t& lo) {
    __nv_bfloat16 h0 = __float2bfloat16(a), h1 = __float2bfloat16(b);
    __nv_bfloat16 l0 = __float2bfloat16(a - __bfloat162float(h0));
    __nv_bfloat16 l1 = __float2bfloat16(b - __bfloat162float(h1));
    lo = (uint32_t)__bfloat16_as_ushort(l0) | ((uint32_t)__bfloat16_as_ushort(l1) << 16);
    return (uint32_t)__bfloat16_as_ushort(h0) | ((uint32_t)__bfloat16_as_ushort(h1) << 16);
}

// ---------------- prologue kernels ----------------
__global__ void init_deg_kernel() {
    int i = blockIdx.x * blockDim.x + threadIdx.x;
    if (i < NN) g_deg[i] = 1.0f;
}
__global__ void count_deg_kernel(const int* __restrict__ ui, const int* __restrict__ ii) {
    int e = blockIdx.x * blockDim.x + threadIdx.x;
    if (e < BB) {
        atomicAdd(&g_deg[ii[e]], 1.0f);
        atomicAdd(&g_deg[ui[e] + BB], 1.0f);
    }
}
__global__ void scanA_kernel() {
    __shared__ int s[256];
    int t = threadIdx.x, b = blockIdx.x;
    int idx = b * 256 + t;
    int val = 0;
    if (idx < NCOMP) {
        int pos = idx < 100000 ? idx : idx + 100000;
        val = __float2int_rn(g_deg[pos]) - 1;
    }
    s[t] = val; __syncthreads();
#pragma unroll
    for (int d = 1; d < 256; d <<= 1) {
        int x = (t >= d) ? s[t - d] : 0;
        __syncthreads(); s[t] += x; __syncthreads();
    }
    if (idx < NCOMP) g_off[idx] = s[t] - val;
    if (t == 255) g_bsum[b] = s[255];
}
__global__ void scanB_kernel(int nb) {
    __shared__ int s[1024];
    int t = threadIdx.x;
    int val = (t < nb) ? g_bsum[t] : 0;
    s[t] = val; __syncthreads();
#pragma unroll
    for (int d = 1; d < 1024; d <<= 1) {
        int x = (t >= d) ? s[t - d] : 0;
        __syncthreads(); s[t] += x; __syncthreads();
    }
    if (t < nb) g_bsum[t] = s[t] - val;
}
__global__ void scanC_kernel() {
    int idx = blockIdx.x * 256 + threadIdx.x;
    if (idx < NCOMP) {
        int v = g_off[idx] + g_bsum[blockIdx.x];
        g_off[idx] = v;
        g_cur[idx] = v;
    }
    if (idx == 0) g_off[NCOMP] = NE;
}
__global__ void dinv_kernel() {
    int i = blockIdx.x * blockDim.x + threadIdx.x;
    if (i < NN) g_deg[i] = 1.0f / sqrtf(g_deg[i]);
}
__global__ void fill_edges_kernel(const int* __restrict__ ui, const int* __restrict__ ii) {
    int e = blockIdx.x * blockDim.x + threadIdx.x;
    if (e >= BB) return;
    int a  = ii[e];
    int up = ui[e] + BB;
    int cb = 100000 + ui[e];
    float norm = g_deg[a] * g_deg[up];
    int i1 = atomicAdd(&g_cur[a], 1);
    g_edge[i1] = make_int2(up, __float_as_int(norm));
    int i2 = atomicAdd(&g_cur[cb], 1);
    g_edge[i2] = make_int2(a, __float_as_int(norm));
}

// Build mma B-operand fragments once per layer (1 CTA/layer; replays GEMM layout)
__global__ void wfrag_kernel(const float* __restrict__ Wall) {
    extern __shared__ char smem[];   // [0,34816) Whi padded, [34816,69632) Wlo
    int layer = blockIdx.x;
    int tid = threadIdx.x;
    for (int idx = tid; idx < 128 * 128; idx += 128) {
        int k = idx >> 7, n = idx & 127;
        float v = Wall[layer * 16384 + idx];
        __nv_bfloat16 hi = __float2bfloat16(v);
        __nv_bfloat16 lo = __float2bfloat16(v - __bfloat162float(hi));
        uint32_t off = ((uint32_t)n * PITCH + (uint32_t)k) * 2;
        *(__nv_bfloat16*)(smem + off)         = hi;
        *(__nv_bfloat16*)(smem + 34816 + off) = lo;
    }
    __syncthreads();
    uint32_t sb = smem_u32(smem);
    int warp = tid >> 5, lane = tid & 31;
    int brow = (lane & 7) + ((lane >> 4) & 1) * 8;
    uint32_t boff = sb + ((uint32_t)brow * PITCH + (uint32_t)(((lane >> 3) & 1) * 8)) * 2;
#pragma unroll
    for (int kk = 0; kk < 2; kk++) {
        int k = warp * 2 + kk;
#pragma unroll
        for (int t = 0; t < 8; t++) {
            uint32_t bk = boff + (uint32_t)t * (16 * PITCH * 2) + (uint32_t)k * 32;
            uint32_t h0, h1, h2, h3, l0, l1, l2, l3;
            ldm_x4(bk,         h0, h1, h2, h3);
            ldm_x4(bk + 34816, l0, l1, l2, l3);
            size_t fi = ((size_t)layer * 64 + (size_t)(k * 8 + t)) * 32 + lane;
            g_Wfrag_hi[fi] = make_uint4(h0, h1, h2, h3);
            g_Wfrag_lo[fi] = make_uint4(l0, l1, l2, l3);
        }
    }
}

// ---------------- shared GEMM mainloop ----------------
#define SM_AHI   0
#define SM_ALO   (TM * PITCH * 2)               // 17408
#define SM_BIAS  (2 * TM * PITCH * 2)           // 34816
#define SM_TOTAL_G (SM_BIAS + 512)              // 35328 (useful gemm)
#define SM_TOTAL_P (SM_BIAS + 1536)             // 36352 (passive: 3 biases)

__device__ __forceinline__ void mainloop(uint32_t sb, int warp, int lane, int layer,
                                         float acc[16][4]) {
    int arow = warp * 16 + (lane & 15);
    uint32_t aoff = sb + SM_AHI + ((uint32_t)arow * PITCH + (uint32_t)((lane >> 4) * 8)) * 2;
    const uint4* __restrict__ wfh = &g_Wfrag_hi[(size_t)layer * 2048 + lane];
    const uint4* __restrict__ wfl = &g_Wfrag_lo[(size_t)layer * 2048 + lane];
#pragma unroll
    for (int i = 0; i < 16; i++) { acc[i][0] = acc[i][1] = acc[i][2] = acc[i][3] = 0.f; }
#pragma unroll
    for (int k = 0; k < 8; k++) {
        uint32_t ah[4], al[4];
        uint32_t ak = aoff + (uint32_t)k * 32;
        ldm_x4(ak, ah[0], ah[1], ah[2], ah[3]);
        ldm_x4(ak + (SM_ALO - SM_AHI), al[0], al[1], al[2], al[3]);
#pragma unroll
        for (int t = 0; t < 8; t++) {
            uint4 bh = wfh[(k * 8 + t) * 32];
            uint4 bl = wfl[(k * 8 + t) * 32];
            mma_bf16(acc[2 * t + 0], ah, bh.x, bh.y);
            mma_bf16(acc[2 * t + 1], ah, bh.z, bh.w);
            mma_bf16(acc[2 * t + 0], al, bh.x, bh.y);
            mma_bf16(acc[2 * t + 1], al, bh.z, bh.w);
            mma_bf16(acc[2 * t + 0], ah, bl.x, bl.y);
            mma_bf16(acc[2 * t + 1], ah, bl.z, bl.w);
        }
    }
}

// ---------------- PASSIVE fused 3-layer chain (non-useful rows) ----------------
__global__ void __launch_bounds__(NTHR, 4)
passive_kernel(const float* __restrict__ UT, const float* __restrict__ IT,
               const int* __restrict__ ui, const int* __restrict__ ii,
               const float* __restrict__ ball, float* __restrict__ out)
{
    extern __shared__ char smem[];
    uint32_t sb = smem_u32(smem);
    int tid = threadIdx.x, warp = tid >> 5, lane = tid & 31;
    int c0 = blockIdx.x * TM;

    if (tid < 128) {
        ((float*)(smem + SM_BIAS))[tid]       = ball[tid];
        ((float*)(smem + SM_BIAS))[128 + tid] = ball[128 + tid];
        ((float*)(smem + SM_BIAS))[256 + tid] = ball[256 + tid];
    }
    __syncthreads();
    const float* bias = (const float*)(smem + SM_BIAS);

#pragma unroll
    for (int i = 0; i < 16; i++) {
        int row = warp * 16 + i;
        int c = c0 + row;
        size_t p = (size_t)c + (c < 100000 ? 100000 : 200000);
        float4 v;
        if (p < BB) v = ((const float4*)(UT + (size_t)ui[p] * DD))[lane];
        else        v = ((const float4*)(IT + (size_t)ii[p - BB] * DD))[lane];
        uint2 hp, lp;
        hp.x = pack_hi2(v.x, v.y, lp.x);
        hp.y = pack_hi2(v.z, v.w, lp.y);
        uint32_t off = ((uint32_t)row * PITCH + (uint32_t)lane * 4) * 2;
        *(uint2*)(smem + SM_AHI + off) = hp;
        *(uint2*)(smem + SM_ALO + off) = lp;
    }
    __syncthreads();

    int grp = lane >> 2, qc = 2 * (lane & 3);
    float acc[16][4];
#pragma unroll 1
    for (int stage = 0; stage < 3; stage++) {
        mainloop(sb, warp, lane, stage, acc);
        if (stage < 2) {
            __syncwarp();
#pragma unroll
            for (int nt = 0; nt < 16; nt++) {
                int col = nt * 8 + qc;
                float bx = bias[stage * 128 + col], by = bias[stage * 128 + col + 1];
                float v0 = fmaxf(acc[nt][0] + bx, 0.f), v1 = fmaxf(acc[nt][1] + by, 0.f);
                float v2 = fmaxf(acc[nt][2] + bx, 0.f), v3 = fmaxf(acc[nt][3] + by, 0.f);
                int rAl = warp * 16 + grp, rBl = rAl + 8;
                uint32_t loA, loB;
                uint32_t hiA = pack_hi2(v0, v1, loA);
                uint32_t hiB = pack_hi2(v2, v3, loB);
                uint32_t offA = ((uint32_t)rAl * PITCH + (uint32_t)col) * 2;
                uint32_t offB = ((uint32_t)rBl * PITCH + (uint32_t)col) * 2;
                *(uint32_t*)(smem + SM_AHI + offA) = hiA;
                *(uint32_t*)(smem + SM_ALO + offA) = loA;
                *(uint32_t*)(smem + SM_AHI + offB) = hiB;
                *(uint32_t*)(smem + SM_ALO + offB) = loB;
            }
            __syncwarp();
        } else {
            int cA = c0 + warp * 16 + grp, cB = cA + 8;
            size_t pA = (size_t)cA + (cA < 100000 ? 100000 : 200000);
            size_t pB = (size_t)cB + (cB < 100000 ? 100000 : 200000);
            float* oA = out + pA * DD;
            float* oB = out + pB * DD;
#pragma unroll
            for (int nt = 0; nt < 16; nt++) {
                int col = nt * 8 + qc;
                float bx = bias[256 + col], by = bias[256 + col + 1];
                *(float2*)(oA + col) =
                    make_float2(fmaxf(acc[nt][0] + bx, 0.f), fmaxf(acc[nt][1] + by, 0.f));
                *(float2*)(oB + col) =
                    make_float2(fmaxf(acc[nt][2] + bx, 0.f), fmaxf(acc[nt][3] + by, 0.f));
            }
        }
    }
}

// ---------------- USEFUL-rows GEMM (compact grid, 3125 CTAs) ----------------
__global__ void __launch_bounds__(NTHR, 4)
gemm_u_kernel(const float* __restrict__ AGGin,
              const int* __restrict__ ui, const int* __restrict__ ii,
              const float* __restrict__ IT, int mode,
              int layer, const float* __restrict__ bprev,
              float* __restrict__ Hout)
{
    extern __shared__ char smem[];
    uint32_t sb = smem_u32(smem);
    int tid = threadIdx.x, warp = tid >> 5, lane = tid & 31;
    int c0 = blockIdx.x * TM;

    ((float*)(smem + SM_BIAS))[tid] = mode ? bprev[tid] : 0.0f;
    __syncthreads();
    const float* bsm = (const float*)(smem + SM_BIAS);

#pragma unroll
    for (int i = 0; i < 16; i++) {
        int row = warp * 16 + i;
        int c = c0 + row;
        size_t p = (size_t)c + (c < 100000 ? 0 : 100000);
        float4 v;
        if (mode == 0) {
            if (p < BB) v = ((const float4*)(AGGin + (size_t)ui[p] * DD))[lane];
            else        v = ((const float4*)(IT    + (size_t)ii[p - BB] * DD))[lane];
        } else {
            v = ((const float4*)(AGGin + p * DD))[lane];
            int cc = lane * 4;
            v.x = fmaxf(v.x + bsm[cc + 0], 0.0f);
            v.y = fmaxf(v.y + bsm[cc + 1], 0.0f);
            v.z = fmaxf(v.z + bsm[cc + 2], 0.0f);
            v.w = fmaxf(v.w + bsm[cc + 3], 0.0f);
        }
        uint2 hp, lp;
        hp.x = pack_hi2(v.x, v.y, lp.x);
        hp.y = pack_hi2(v.z, v.w, lp.y);
        uint32_t off = ((uint32_t)row * PITCH + (uint32_t)lane * 4) * 2;
        *(uint2*)(smem + SM_AHI + off) = hp;
        *(uint2*)(smem + SM_ALO + off) = lp;
    }
    __syncthreads();

    float acc[16][4];
    mainloop(sb, warp, lane, layer, acc);

    int grp = lane >> 2, qc = 2 * (lane & 3);
    int cA = c0 + warp * 16 + grp, cB = cA + 8;
    size_t pA = (size_t)cA + (cA < 100000 ? 0 : 100000);
    size_t pB = (size_t)cB + (cB < 100000 ? 0 : 100000);
    float* D0 = Hout + pA * DD;
    float* D1 = Hout + pB * DD;
#pragma unroll
    for (int nt = 0; nt < 16; nt++) {
        int col = nt * 8 + qc;
        *(float2*)(D0 + col) = make_float2(acc[nt][0], acc[nt][1]);
        *(float2*)(D1 + col) = make_float2(acc[nt][2], acc[nt][3]);
    }
}

// ---------------- pull aggregation (one warp per useful row) ----------------
__global__ void pull_kernel(const float* __restrict__ Hin,
                            const float* __restrict__ dinv,
                            float* __restrict__ AGG) {
    int t = blockIdx.x * blockDim.x + threadIdx.x;
    int c = t >> 5;
    if (c >= NCOMP) return;
    int lane = t & 31;
    size_t p = (size_t)c + (c < 100000 ? 0 : 100000);
    float dv = dinv[p]; float d2 = dv * dv;
    float4 v = ((const float4*)(Hin + p * DD))[lane];
    v.x *= d2; v.y *= d2; v.z *= d2; v.w *= d2;
    int e0 = g_off[c], e1 = g_off[c + 1];
    for (int j = e0; j < e1; j++) {
        int2 en = g_edge[j];
        float nm = __int_as_float(en.y);
        float4 hv = ((const float4*)(Hin + (size_t)en.x * DD))[lane];
        v.x += nm * hv.x; v.y += nm * hv.y;
        v.z += nm * hv.z; v.w += nm * hv.w;
    }
    ((float4*)(AGG + p * DD))[lane] = v;
}

// final pull for useful rows: out = relu(d2*H[p] + sum norm*H[nbr] + b2)
__global__ void final_pull_kernel(const float* __restrict__ Hin,
                                  const float* __restrict__ dinv,
                                  const float* __restrict__ b2,
                                  float* __restrict__ out) {
    int t = blockIdx.x * blockDim.x + threadIdx.x;
    int c = t >> 5;
    if (c >= NCOMP) return;
    int lane = t & 31;
    size_t p = (size_t)c + (c < 100000 ? 0 : 100000);
    float dv = dinv[p]; float d2 = dv * dv;
    float4 v = ((const float4*)(Hin + p * DD))[lane];
    v.x *= d2; v.y *= d2; v.z *= d2; v.w *= d2;
    int e0 = g_off[c], e1 = g_off[c + 1];
    for (int j = e0; j < e1; j++) {
        int2 en = g_edge[j];
        float nm = __int_as_float(en.y);
        float4 hv = ((const float4*)(Hin + (size_t)en.x * DD))[lane];
        v.x += nm * hv.x; v.y += nm * hv.y;
        v.z += nm * hv.z; v.w += nm * hv.w;
    }
    float4 bb = ((const float4*)b2)[lane];
    v.x = fmaxf(v.x + bb.x, 0.0f);
    v.y = fmaxf(v.y + bb.y, 0.0f);
    v.z = fmaxf(v.z + bb.z, 0.0f);
    v.w = fmaxf(v.w + bb.w, 0.0f);
    ((float4*)(out + p * DD))[lane] = v;
}

extern "C" void kernel_launch(void* const* d_in, const int* in_sizes, int n_in,
                              void* d_out, int out_size) {
    const int*   ui   = (const int*)d_in[0];
    const int*   ii   = (const int*)d_in[1];
    const float* UT   = (const float*)d_in[2];
    const float* IT   = (const float*)d_in[3];
    const float* Wall = (const float*)d_in[4];
    const float* ball = (const float*)d_in[5];
    float* out = (float*)d_out;

    float *deg, *H, *P0, *P1;
    cudaGetSymbolAddress((void**)&deg, g_deg);
    cudaGetSymbolAddress((void**)&H,   g_H);
    cudaGetSymbolAddress((void**)&P0,  g_P0);
    cudaGetSymbolAddress((void**)&P1,  g_P1);

    cudaFuncSetAttribute(gemm_u_kernel,  cudaFuncAttributeMaxDynamicSharedMemorySize, SM_TOTAL_G);
    cudaFuncSetAttribute(passive_kernel, cudaFuncAttributeMaxDynamicSharedMemorySize, SM_TOTAL_P);
    cudaFuncSetAttribute(wfrag_kernel,   cudaFuncAttributeMaxDynamicSharedMemorySize, 69632);

    const int NSCB = (NCOMP + 255) / 256;   // 782
    const int PBLK = (NCOMP * 32 + 255) / 256;
    const int GB   = NCOMP / TM;            // 3125

    // Side stream + fork/join events for the independent passive chain.
    // Created per call (kernel_launch runs only for the correctness pass and
    // the capture pass); no device memory is allocated.
    cudaStream_t s2;
    cudaStreamCreateWithFlags(&s2, cudaStreamNonBlocking);
    cudaEvent_t evFork, evJoin;
    cudaEventCreateWithFlags(&evFork, cudaEventDisableTiming);
    cudaEventCreateWithFlags(&evJoin, cudaEventDisableTiming);

    init_deg_kernel<<<(NN + 255) / 256, 256>>>();
    count_deg_kernel<<<(BB + 255) / 256, 256>>>(ui, ii);
    scanA_kernel<<<NSCB, 256>>>();
    scanB_kernel<<<1, 1024>>>(NSCB);
    scanC_kernel<<<NSCB, 256>>>();
    dinv_kernel<<<(NN + 255) / 256, 256>>>();
    fill_edges_kernel<<<(BB + 255) / 256, 256>>>(ui, ii);
    wfrag_kernel<<<3, 128, 69632>>>(Wall);

    // fork: passive chain on s2, concurrent with the useful chain
    cudaEventRecord(evFork, 0);
    cudaStreamWaitEvent(s2, evFork, 0);
    passive_kernel<<<GB, NTHR, SM_TOTAL_P, s2>>>(UT, IT, ui, ii, ball, out);
    cudaEventRecord(evJoin, s2);

    // useful half: (GEMM -> pull) x3 on the main stream
    gemm_u_kernel<<<GB, NTHR, SM_TOTAL_G>>>(UT, ui, ii, IT, 0, 0, nullptr, P0);
    pull_kernel<<<PBLK, 256>>>(P0, deg, P1);
    gemm_u_kernel<<<GB, NTHR, SM_TOTAL_G>>>(P1, ui, ii, nullptr, 1, 1, ball, H);
    pull_kernel<<<PBLK, 256>>>(H, deg, P0);
    gemm_u_kernel<<<GB, NTHR, SM_TOTAL_G>>>(P0, ui, ii, nullptr, 1, 2, ball + DD, P1);
    final_pull_kernel<<<PBLK, 256>>>(P1, deg, ball + 2 * DD, out);

    // join: main stream waits for passive completion
    cudaStreamWaitEvent(0, evJoin, 0);
}

// round 17
// speedup vs baseline: 1.7761x; 1.0170x over previous
#include <cuda_runtime.h>
#include <cuda_bf16.h>
#include <cstdint>

#define BB 200000      // batch size
#define NN 400000      // nodes = 2*BB
#define DD 128         // embedding dim
#define PITCH 136      // padded bf16 pitch for smem tiles
#define TM 64          // GEMM tile rows per CTA
#define NTHR 128       // threads per GEMM CTA (4 warps)
#define NCOMP 200000   // useful rows, compact: [0,100k) u [200k,300k)
#define NE (2 * BB)    // directed edges

// ---------------- scratch (device globals; no allocs allowed) ----------------
__device__ float g_deg[NN];                       // degree -> dinv (in place)
__device__ float g_H [(size_t)NN * DD];           // buffer C
__device__ float g_P0[(size_t)NN * DD];           // buffer A
__device__ float g_P1[(size_t)NN * DD];           // buffer B
__device__ uint4 g_Wfrag_hi[3 * 64 * 32];         // mma B fragments, hi (32KB/layer)
__device__ uint4 g_Wfrag_lo[3 * 64 * 32];         // mma B fragments, lo
__device__ int  g_off[NCOMP + 1];                 // CSR offsets (compact)
__device__ int  g_cur[NCOMP];                     // fill cursors
__device__ int  g_bsum[800];                      // scan block sums
__device__ int2 g_edge[NE];                       // (nbr position, norm bits)

// ---------------- helpers ----------------
__device__ __forceinline__ uint32_t smem_u32(const void* p) {
    uint32_t a;
    asm("{ .reg .u64 t; cvta.to.shared.u64 t, %1; cvt.u32.u64 %0, t; }" : "=r"(a) : "l"(p));
    return a;
}
__device__ __forceinline__ void ldm_x4(uint32_t a, uint32_t& r0, uint32_t& r1,
                                       uint32_t& r2, uint32_t& r3) {
    asm volatile("ldmatrix.sync.aligned.m8n8.x4.shared.b16 {%0,%1,%2,%3}, [%4];"
                 : "=r"(r0), "=r"(r1), "=r"(r2), "=r"(r3) : "r"(a));
}
__device__ __forceinline__ void mma_bf16(float* c, const uint32_t* a, uint32_t b0, uint32_t b1) {
    asm volatile("mma.sync.aligned.m16n8k16.row.col.f32.bf16.bf16.f32 "
                 "{%0,%1,%2,%3}, {%4,%5,%6,%7}, {%8,%9}, {%0,%1,%2,%3};"
                 : "+f"(c[0]), "+f"(c[1]), "+f"(c[2]), "+f"(c[3])
                 : "r"(a[0]), "r"(a[1]), "r"(a[2]), "r"(a[3]), "r"(b0), "r"(b1));
}
__device__ __forceinline__ uint32_t pack_hi2(float a, float b, uint32_t& lo) {
    __nv_bfloat16 h0 = __float2bfloat16(a), h1 = __float2bfloat16(b);
    __nv_bfloat16 l0 = __float2bfloat16(a - __bfloat162float(h0));
    __nv_bfloat16 l1 = __float2bfloat16(b - __bfloat162float(h1));
    lo = (uint32_t)__bfloat16_as_ushort(l0) | ((uint32_t)__bfloat16_as_ushort(l1) << 16);
    return (uint32_t)__bfloat16_as_ushort(h0) | ((uint32_t)__bfloat16_as_ushort(h1) << 16);
}

// ---------------- prologue kernels ----------------
__global__ void init_deg_kernel() {
    int i = blockIdx.x * blockDim.x + threadIdx.x;
    if (i < NN) g_deg[i] = 1.0f;
}
__global__ void count_deg_kernel(const int* __restrict__ ui, const int* __restrict__ ii) {
    int e = blockIdx.x * blockDim.x + threadIdx.x;
    if (e < BB) {
        atomicAdd(&g_deg[ii[e]], 1.0f);
        atomicAdd(&g_deg[ui[e] + BB], 1.0f);
    }
}
__global__ void scanA_kernel() {
    __shared__ int s[256];
    int t = threadIdx.x, b = blockIdx.x;
    int idx = b * 256 + t;
    int val = 0;
    if (idx < NCOMP) {
        int pos = idx < 100000 ? idx : idx + 100000;
        val = __float2int_rn(g_deg[pos]) - 1;
    }
    s[t] = val; __syncthreads();
#pragma unroll
    for (int d = 1; d < 256; d <<= 1) {
        int x = (t >= d) ? s[t - d] : 0;
        __syncthreads(); s[t] += x; __syncthreads();
    }
    if (idx < NCOMP) g_off[idx] = s[t] - val;
    if (t == 255) g_bsum[b] = s[255];
}
__global__ void scanB_kernel(int nb) {
    __shared__ int s[1024];
    int t = threadIdx.x;
    int val = (t < nb) ? g_bsum[t] : 0;
    s[t] = val; __syncthreads();
#pragma unroll
    for (int d = 1; d < 1024; d <<= 1) {
        int x = (t >= d) ? s[t - d] : 0;
        __syncthreads(); s[t] += x; __syncthreads();
    }
    if (t < nb) g_bsum[t] = s[t] - val;
}
__global__ void scanC_kernel() {
    int idx = blockIdx.x * 256 + threadIdx.x;
    if (idx < NCOMP) {
        int v = g_off[idx] + g_bsum[blockIdx.x];
        g_off[idx] = v;
        g_cur[idx] = v;
    }
    if (idx == 0) g_off[NCOMP] = NE;
}
__global__ void dinv_kernel() {
    int i = blockIdx.x * blockDim.x + threadIdx.x;
    if (i < NN) g_deg[i] = 1.0f / sqrtf(g_deg[i]);
}
__global__ void fill_edges_kernel(const int* __restrict__ ui, const int* __restrict__ ii) {
    int e = blockIdx.x * blockDim.x + threadIdx.x;
    if (e >= BB) return;
    int a  = ii[e];
    int up = ui[e] + BB;
    int cb = 100000 + ui[e];
    float norm = g_deg[a] * g_deg[up];
    int i1 = atomicAdd(&g_cur[a], 1);
    g_edge[i1] = make_int2(up, __float_as_int(norm));
    int i2 = atomicAdd(&g_cur[cb], 1);
    g_edge[i2] = make_int2(a, __float_as_int(norm));
}

// Build mma B-operand fragments once per layer (1 CTA/layer; replays GEMM layout)
__global__ void wfrag_kernel(const float* __restrict__ Wall) {
    extern __shared__ char smem[];   // [0,34816) Whi padded, [34816,69632) Wlo
    int layer = blockIdx.x;
    int tid = threadIdx.x;
    for (int idx = tid; idx < 128 * 128; idx += 128) {
        int k = idx >> 7, n = idx & 127;
        float v = Wall[layer * 16384 + idx];
        __nv_bfloat16 hi = __float2bfloat16(v);
        __nv_bfloat16 lo = __float2bfloat16(v - __bfloat162float(hi));
        uint32_t off = ((uint32_t)n * PITCH + (uint32_t)k) * 2;
        *(__nv_bfloat16*)(smem + off)         = hi;
        *(__nv_bfloat16*)(smem + 34816 + off) = lo;
    }
    __syncthreads();
    uint32_t sb = smem_u32(smem);
    int warp = tid >> 5, lane = tid & 31;
    int brow = (lane & 7) + ((lane >> 4) & 1) * 8;
    uint32_t boff = sb + ((uint32_t)brow * PITCH + (uint32_t)(((lane >> 3) & 1) * 8)) * 2;
#pragma unroll
    for (int kk = 0; kk < 2; kk++) {
        int k = warp * 2 + kk;
#pragma unroll
        for (int t = 0; t < 8; t++) {
            uint32_t bk = boff + (uint32_t)t * (16 * PITCH * 2) + (uint32_t)k * 32;
            uint32_t h0, h1, h2, h3, l0, l1, l2, l3;
            ldm_x4(bk,         h0, h1, h2, h3);
            ldm_x4(bk + 34816, l0, l1, l2, l3);
            size_t fi = ((size_t)layer * 64 + (size_t)(k * 8 + t)) * 32 + lane;
            g_Wfrag_hi[fi] = make_uint4(h0, h1, h2, h3);
            g_Wfrag_lo[fi] = make_uint4(l0, l1, l2, l3);
        }
    }
}

// ---------------- shared GEMM mainloop ----------------
#define SM_AHI   0
#define SM_ALO   (TM * PITCH * 2)               // 17408
#define SM_BIAS  (2 * TM * PITCH * 2)           // 34816
#define SM_TOTAL_G (SM_BIAS + 512)              // 35328 (useful gemm)
#define SM_TOTAL_P (SM_BIAS + 1536)             // 36352 (passive: 3 biases)

__device__ __forceinline__ void mainloop(uint32_t sb, int warp, int lane, int layer,
                                         float acc[16][4]) {
    int arow = warp * 16 + (lane & 15);
    uint32_t aoff = sb + SM_AHI + ((uint32_t)arow * PITCH + (uint32_t)((lane >> 4) * 8)) * 2;
    const uint4* __restrict__ wfh = &g_Wfrag_hi[(size_t)layer * 2048 + lane];
    const uint4* __restrict__ wfl = &g_Wfrag_lo[(size_t)layer * 2048 + lane];
#pragma unroll
    for (int i = 0; i < 16; i++) { acc[i][0] = acc[i][1] = acc[i][2] = acc[i][3] = 0.f; }
#pragma unroll
    for (int k = 0; k < 8; k++) {
        uint32_t ah[4], al[4];
        uint32_t ak = aoff + (uint32_t)k * 32;
        ldm_x4(ak, ah[0], ah[1], ah[2], ah[3]);
        ldm_x4(ak + (SM_ALO - SM_AHI), al[0], al[1], al[2], al[3]);
#pragma unroll
        for (int t = 0; t < 8; t++) {
            uint4 bh = wfh[(k * 8 + t) * 32];
            uint4 bl = wfl[(k * 8 + t) * 32];
            mma_bf16(acc[2 * t + 0], ah, bh.x, bh.y);
            mma_bf16(acc[2 * t + 1], ah, bh.z, bh.w);
            mma_bf16(acc[2 * t + 0], al, bh.x, bh.y);
            mma_bf16(acc[2 * t + 1], al, bh.z, bh.w);
            mma_bf16(acc[2 * t + 0], ah, bl.x, bl.y);
            mma_bf16(acc[2 * t + 1], ah, bl.z, bl.w);
        }
    }
}

// ---------------- PASSIVE fused 3-layer chain (non-useful rows) ----------------
__global__ void __launch_bounds__(NTHR, 4)
passive_kernel(const float* __restrict__ UT, const float* __restrict__ IT,
               const int* __restrict__ ui, const int* __restrict__ ii,
               const float* __restrict__ ball, float* __restrict__ out)
{
    extern __shared__ char smem[];
    uint32_t sb = smem_u32(smem);
    int tid = threadIdx.x, warp = tid >> 5, lane = tid & 31;
    int c0 = blockIdx.x * TM;

    if (tid < 128) {
        ((float*)(smem + SM_BIAS))[tid]       = ball[tid];
        ((float*)(smem + SM_BIAS))[128 + tid] = ball[128 + tid];
        ((float*)(smem + SM_BIAS))[256 + tid] = ball[256 + tid];
    }
    __syncthreads();
    const float* bias = (const float*)(smem + SM_BIAS);

#pragma unroll
    for (int i = 0; i < 16; i++) {
        int row = warp * 16 + i;
        int c = c0 + row;
        size_t p = (size_t)c + (c < 100000 ? 100000 : 200000);
        float4 v;
        if (p < BB) v = ((const float4*)(UT + (size_t)ui[p] * DD))[lane];
        else        v = ((const float4*)(IT + (size_t)ii[p - BB] * DD))[lane];
        uint2 hp, lp;
        hp.x = pack_hi2(v.x, v.y, lp.x);
        hp.y = pack_hi2(v.z, v.w, lp.y);
        uint32_t off = ((uint32_t)row * PITCH + (uint32_t)lane * 4) * 2;
        *(uint2*)(smem + SM_AHI + off) = hp;
        *(uint2*)(smem + SM_ALO + off) = lp;
    }
    __syncthreads();

    int grp = lane >> 2, qc = 2 * (lane & 3);
    float acc[16][4];
#pragma unroll 1
    for (int stage = 0; stage < 3; stage++) {
        mainloop(sb, warp, lane, stage, acc);
        if (stage < 2) {
            __syncwarp();
#pragma unroll
            for (int nt = 0; nt < 16; nt++) {
                int col = nt * 8 + qc;
                float bx = bias[stage * 128 + col], by = bias[stage * 128 + col + 1];
                float v0 = fmaxf(acc[nt][0] + bx, 0.f), v1 = fmaxf(acc[nt][1] + by, 0.f);
                float v2 = fmaxf(acc[nt][2] + bx, 0.f), v3 = fmaxf(acc[nt][3] + by, 0.f);
                int rAl = warp * 16 + grp, rBl = rAl + 8;
                uint32_t loA, loB;
                uint32_t hiA = pack_hi2(v0, v1, loA);
                uint32_t hiB = pack_hi2(v2, v3, loB);
                uint32_t offA = ((uint32_t)rAl * PITCH + (uint32_t)col) * 2;
                uint32_t offB = ((uint32_t)rBl * PITCH + (uint32_t)col) * 2;
                *(uint32_t*)(smem + SM_AHI + offA) = hiA;
                *(uint32_t*)(smem + SM_ALO + offA) = loA;
                *(uint32_t*)(smem + SM_AHI + offB) = hiB;
                *(uint32_t*)(smem + SM_ALO + offB) = loB;
            }
            __syncwarp();
        } else {
            int cA = c0 + warp * 16 + grp, cB = cA + 8;
            size_t pA = (size_t)cA + (cA < 100000 ? 100000 : 200000);
            size_t pB = (size_t)cB + (cB < 100000 ? 100000 : 200000);
            float* oA = out + pA * DD;
            float* oB = out + pB * DD;
#pragma unroll
            for (int nt = 0; nt < 16; nt++) {
                int col = nt * 8 + qc;
                float bx = bias[256 + col], by = bias[256 + col + 1];
                *(float2*)(oA + col) =
                    make_float2(fmaxf(acc[nt][0] + bx, 0.f), fmaxf(acc[nt][1] + by, 0.f));
                *(float2*)(oB + col) =
                    make_float2(fmaxf(acc[nt][2] + bx, 0.f), fmaxf(acc[nt][3] + by, 0.f));
            }
        }
    }
}

// ---------------- USEFUL-rows GEMM (compact grid, 3125 CTAs) ----------------
__global__ void __launch_bounds__(NTHR, 4)
gemm_u_kernel(const float* __restrict__ AGGin,
              const int* __restrict__ ui, const int* __restrict__ ii,
              const float* __restrict__ IT, int mode,
              int layer, const float* __restrict__ bprev,
              float* __restrict__ Hout)
{
    extern __shared__ char smem[];
    uint32_t sb = smem_u32(smem);
    int tid = threadIdx.x, warp = tid >> 5, lane = tid & 31;
    int c0 = blockIdx.x * TM;

    ((float*)(smem + SM_BIAS))[tid] = mode ? bprev[tid] : 0.0f;
    __syncthreads();
    const float* bsm = (const float*)(smem + SM_BIAS);

#pragma unroll
    for (int i = 0; i < 16; i++) {
        int row = warp * 16 + i;
        int c = c0 + row;
        size_t p = (size_t)c + (c < 100000 ? 0 : 100000);
        float4 v;
        if (mode == 0) {
            if (p < BB) v = ((const float4*)(AGGin + (size_t)ui[p] * DD))[lane];
            else        v = ((const float4*)(IT    + (size_t)ii[p - BB] * DD))[lane];
        } else {
            v = ((const float4*)(AGGin + p * DD))[lane];
            int cc = lane * 4;
            v.x = fmaxf(v.x + bsm[cc + 0], 0.0f);
            v.y = fmaxf(v.y + bsm[cc + 1], 0.0f);
            v.z = fmaxf(v.z + bsm[cc + 2], 0.0f);
            v.w = fmaxf(v.w + bsm[cc + 3], 0.0f);
        }
        uint2 hp, lp;
        hp.x = pack_hi2(v.x, v.y, lp.x);
        hp.y = pack_hi2(v.z, v.w, lp.y);
        uint32_t off = ((uint32_t)row * PITCH + (uint32_t)lane * 4) * 2;
        *(uint2*)(smem + SM_AHI + off) = hp;
        *(uint2*)(smem + SM_ALO + off) = lp;
    }
    __syncthreads();

    float acc[16][4];
    mainloop(sb, warp, lane, layer, acc);

    int grp = lane >> 2, qc = 2 * (lane & 3);
    int cA = c0 + warp * 16 + grp, cB = cA + 8;
    size_t pA = (size_t)cA + (cA < 100000 ? 0 : 100000);
    size_t pB = (size_t)cB + (cB < 100000 ? 0 : 100000);
    float* D0 = Hout + pA * DD;
    float* D1 = Hout + pB * DD;
#pragma unroll
    for (int nt = 0; nt < 16; nt++) {
        int col = nt * 8 + qc;
        *(float2*)(D0 + col) = make_float2(acc[nt][0], acc[nt][1]);
        *(float2*)(D1 + col) = make_float2(acc[nt][2], acc[nt][3]);
    }
}

// ---------------- pull aggregation (one warp per useful row) ----------------
__global__ void pull_kernel(const float* __restrict__ Hin,
                            const float* __restrict__ dinv,
                            float* __restrict__ AGG) {
    int t = blockIdx.x * blockDim.x + threadIdx.x;
    int c = t >> 5;
    if (c >= NCOMP) return;
    int lane = t & 31;
    size_t p = (size_t)c + (c < 100000 ? 0 : 100000);
    float dv = dinv[p]; float d2 = dv * dv;
    float4 v = ((const float4*)(Hin + p * DD))[lane];
    v.x *= d2; v.y *= d2; v.z *= d2; v.w *= d2;
    int e0 = g_off[c], e1 = g_off[c + 1];
    for (int j = e0; j < e1; j++) {
        int2 en = g_edge[j];
        float nm = __int_as_float(en.y);
        float4 hv = ((const float4*)(Hin + (size_t)en.x * DD))[lane];
        v.x += nm * hv.x; v.y += nm * hv.y;
        v.z += nm * hv.z; v.w += nm * hv.w;
    }
    ((float4*)(AGG + p * DD))[lane] = v;
}

// final pull for useful rows: out = relu(d2*H[p] + sum norm*H[nbr] + b2)
__global__ void final_pull_kernel(const float* __restrict__ Hin,
                                  const float* __restrict__ dinv,
                                  const float* __restrict__ b2,
                                  float* __restrict__ out) {
    int t = blockIdx.x * blockDim.x + threadIdx.x;
    int c = t >> 5;
    if (c >= NCOMP) return;
    int lane = t & 31;
    size_t p = (size_t)c + (c < 100000 ? 0 : 100000);
    float dv = dinv[p]; float d2 = dv * dv;
    float4 v = ((const float4*)(Hin + p * DD))[lane];
    v.x *= d2; v.y *= d2; v.z *= d2; v.w *= d2;
    int e0 = g_off[c], e1 = g_off[c + 1];
    for (int j = e0; j < e1; j++) {
        int2 en = g_edge[j];
        float nm = __int_as_float(en.y);
        float4 hv = ((const float4*)(Hin + (size_t)en.x * DD))[lane];
        v.x += nm * hv.x; v.y += nm * hv.y;
        v.z += nm * hv.z; v.w += nm * hv.w;
    }
    float4 bb = ((const float4*)b2)[lane];
    v.x = fmaxf(v.x + bb.x, 0.0f);
    v.y = fmaxf(v.y + bb.y, 0.0f);
    v.z = fmaxf(v.z + bb.z, 0.0f);
    v.w = fmaxf(v.w + bb.w, 0.0f);
    ((float4*)(out + p * DD))[lane] = v;
}

extern "C" void kernel_launch(void* const* d_in, const int* in_sizes, int n_in,
                              void* d_out, int out_size) {
    const int*   ui   = (const int*)d_in[0];
    const int*   ii   = (const int*)d_in[1];
    const float* UT   = (const float*)d_in[2];
    const float* IT   = (const float*)d_in[3];
    const float* Wall = (const float*)d_in[4];
    const float* ball = (const float*)d_in[5];
    float* out = (float*)d_out;

    float *deg, *H, *P0, *P1;
    cudaGetSymbolAddress((void**)&deg, g_deg);
    cudaGetSymbolAddress((void**)&H,   g_H);
    cudaGetSymbolAddress((void**)&P0,  g_P0);
    cudaGetSymbolAddress((void**)&P1,  g_P1);

    cudaFuncSetAttribute(gemm_u_kernel,  cudaFuncAttributeMaxDynamicSharedMemorySize, SM_TOTAL_G);
    cudaFuncSetAttribute(passive_kernel, cudaFuncAttributeMaxDynamicSharedMemorySize, SM_TOTAL_P);
    cudaFuncSetAttribute(wfrag_kernel,   cudaFuncAttributeMaxDynamicSharedMemorySize, 69632);

    const int NSCB = (NCOMP + 255) / 256;   // 782
    const int PBLK = (NCOMP * 32 + 255) / 256;
    const int GB   = NCOMP / TM;            // 3125

    // ONE side stream (the configuration proven clean by the allocation guards
    // in R15); all side work — prologue chain then passive — runs on it.
    cudaStream_t s2;
    cudaStreamCreateWithFlags(&s2, cudaStreamNonBlocking);
    cudaEvent_t evFork, evWf, evEdges, evSide;
    cudaEventCreateWithFlags(&evFork,  cudaEventDisableTiming);
    cudaEventCreateWithFlags(&evWf,    cudaEventDisableTiming);
    cudaEventCreateWithFlags(&evEdges, cudaEventDisableTiming);
    cudaEventCreateWithFlags(&evSide,  cudaEventDisableTiming);

    // fork s2 off the main stream head (single capture root)
    cudaEventRecord(evFork, 0);
    cudaStreamWaitEvent(s2, evFork, 0);

    // s2: deg/scan/CSR chain (only pull kernels depend on it)
    init_deg_kernel<<<(NN + 255) / 256, 256, 0, s2>>>();
    count_deg_kernel<<<(BB + 255) / 256, 256, 0, s2>>>(ui, ii);
    scanA_kernel<<<NSCB, 256, 0, s2>>>();
    scanB_kernel<<<1, 1024, 0, s2>>>(NSCB);
    scanC_kernel<<<NSCB, 256, 0, s2>>>();
    dinv_kernel<<<(NN + 255) / 256, 256, 0, s2>>>();
    fill_edges_kernel<<<(BB + 255) / 256, 256, 0, s2>>>(ui, ii);
    cudaEventRecord(evEdges, s2);

    // main: wfrag (needed by every MMA kernel)
    wfrag_kernel<<<3, 128, 69632>>>(Wall);
    cudaEventRecord(evWf, 0);

    // s2: passive fused chain after its prologue + wfrag
    cudaStreamWaitEvent(s2, evWf, 0);
    passive_kernel<<<GB, NTHR, SM_TOTAL_P, s2>>>(UT, IT, ui, ii, ball, out);
    cudaEventRecord(evSide, s2);

    // main: useful chain
    gemm_u_kernel<<<GB, NTHR, SM_TOTAL_G>>>(UT, ui, ii, IT, 0, 0, nullptr, P0);
    cudaStreamWaitEvent(0, evEdges, 0);   // CSR + dinv ready before pull0
    pull_kernel<<<PBLK, 256>>>(P0, deg, P1);
    gemm_u_kernel<<<GB, NTHR, SM_TOTAL_G>>>(P1, ui, ii, nullptr, 1, 1, ball, H);
    pull_kernel<<<PBLK, 256>>>(H, deg, P0);
    gemm_u_kernel<<<GB, NTHR, SM_TOTAL_G>>>(P0, ui, ii, nullptr, 1, 2, ball + DD, P1);
    final_pull_kernel<<<PBLK, 256>>>(P1, deg, ball + 2 * DD, out);

    // join side stream
    cudaStreamWaitEvent(0, evSide, 0);
}